// round 2
// baseline (speedup 1.0000x reference)
#include <cuda_runtime.h>
#include <math.h>

// Problem constants
#define BB 4
#define SS 1024
#define CC 1280
#define HH 20
#define DD 64
#define ATT_SCALE 0.125f              // 64^-0.5
#define SHIFTV 0.6931471805599453f    // log(2)
#define EPSV 1e-5f

// ---------------- scratch (static device allocations are allowed) -----------
__device__ float g_q[BB*SS*CC];
__device__ float g_k[BB*SS*CC];
__device__ float g_v[BB*SS*CC];
__device__ float g_attn[BB*SS*CC];
__device__ float g_mean[2*BB*CC];
__device__ float g_std[2*BB*CC];
__device__ float g_scl[2*BB*CC];
__device__ float g_shf[2*BB*CC];

// ---------------------------------------------------------------------------
// SGEMM: Cout[m][n] = sum_k A[m][k] * W[n][k] (+ bias[n])
// A: [M x K] row-major, W: [N x K] row-major (i.e. computes A @ W^T)
// Block tile 128x128, BK=16, 256 threads, 8x8 per-thread register tile.
// ---------------------------------------------------------------------------
__device__ __forceinline__ void sgemm_body(
    const float* __restrict__ A, const float* __restrict__ W,
    const float* __restrict__ bias, float* __restrict__ Cout,
    int K, int N)
{
    __shared__ float As[16][132];
    __shared__ float Bs[16][132];

    const int tid = threadIdx.x;
    const int tx  = tid & 15;
    const int ty  = tid >> 4;
    const int m0  = blockIdx.y * 128;
    const int n0  = blockIdx.x * 128;

    const int lrow = tid >> 2;          // 0..63
    const int lk4  = (tid & 3) << 2;    // 0,4,8,12

    const float* Ap = A + (size_t)(m0 + lrow) * K + lk4;
    const float* Bp = W + (size_t)(n0 + lrow) * K + lk4;

    float4 pa0 = *(const float4*)(Ap);
    float4 pa1 = *(const float4*)(Ap + (size_t)64 * K);
    float4 pb0 = *(const float4*)(Bp);
    float4 pb1 = *(const float4*)(Bp + (size_t)64 * K);

    float acc[8][8];
#pragma unroll
    for (int j = 0; j < 8; j++)
#pragma unroll
        for (int i = 0; i < 8; i++) acc[j][i] = 0.f;

    const int KT = K >> 4;
    for (int kt = 0; kt < KT; kt++) {
        As[lk4+0][lrow]    = pa0.x; As[lk4+1][lrow]    = pa0.y;
        As[lk4+2][lrow]    = pa0.z; As[lk4+3][lrow]    = pa0.w;
        As[lk4+0][lrow+64] = pa1.x; As[lk4+1][lrow+64] = pa1.y;
        As[lk4+2][lrow+64] = pa1.z; As[lk4+3][lrow+64] = pa1.w;
        Bs[lk4+0][lrow]    = pb0.x; Bs[lk4+1][lrow]    = pb0.y;
        Bs[lk4+2][lrow]    = pb0.z; Bs[lk4+3][lrow]    = pb0.w;
        Bs[lk4+0][lrow+64] = pb1.x; Bs[lk4+1][lrow+64] = pb1.y;
        Bs[lk4+2][lrow+64] = pb1.z; Bs[lk4+3][lrow+64] = pb1.w;
        __syncthreads();

        if (kt + 1 < KT) {
            const float* Ap2 = Ap + (kt + 1) * 16;
            const float* Bp2 = Bp + (kt + 1) * 16;
            pa0 = *(const float4*)(Ap2);
            pa1 = *(const float4*)(Ap2 + (size_t)64 * K);
            pb0 = *(const float4*)(Bp2);
            pb1 = *(const float4*)(Bp2 + (size_t)64 * K);
        }

#pragma unroll
        for (int kk = 0; kk < 16; kk++) {
            float av[8], bv[8];
            *(float4*)&av[0] = *(const float4*)&As[kk][ty * 8];
            *(float4*)&av[4] = *(const float4*)&As[kk][ty * 8 + 4];
            *(float4*)&bv[0] = *(const float4*)&Bs[kk][tx * 8];
            *(float4*)&bv[4] = *(const float4*)&Bs[kk][tx * 8 + 4];
#pragma unroll
            for (int j = 0; j < 8; j++)
#pragma unroll
                for (int i = 0; i < 8; i++)
                    acc[j][i] = fmaf(av[j], bv[i], acc[j][i]);
        }
        __syncthreads();
    }

    float breg[8];
#pragma unroll
    for (int i = 0; i < 8; i++) breg[i] = bias ? bias[n0 + tx * 8 + i] : 0.f;

#pragma unroll
    for (int j = 0; j < 8; j++) {
        float* Crow = Cout + (size_t)(m0 + ty * 8 + j) * N + n0 + tx * 8;
        float4 o0 = make_float4(acc[j][0] + breg[0], acc[j][1] + breg[1],
                                acc[j][2] + breg[2], acc[j][3] + breg[3]);
        float4 o1 = make_float4(acc[j][4] + breg[4], acc[j][5] + breg[5],
                                acc[j][6] + breg[6], acc[j][7] + breg[7]);
        *(float4*)Crow       = o0;
        *(float4*)(Crow + 4) = o1;
    }
}

__global__ __launch_bounds__(256) void k_qkv(
    const float* __restrict__ X, const float* __restrict__ Wq,
    const float* __restrict__ Wk, const float* __restrict__ Wv)
{
    const float* W;
    float* O;
    if (blockIdx.z == 0)      { W = Wq; O = g_q; }
    else if (blockIdx.z == 1) { W = Wk; O = g_k; }
    else                      { W = Wv; O = g_v; }
    sgemm_body(X, W, nullptr, O, CC, CC);
}

__global__ __launch_bounds__(256) void k_proj_out(
    const float* __restrict__ Wo, const float* __restrict__ bo,
    float* __restrict__ out)
{
    sgemm_body(g_attn, Wo, bo, out, CC, CC);
}

// ---------------------------------------------------------------------------
// AdaIN: stats over sequence axis (unbiased var), per (tensor z, batch b, ch c)
// ---------------------------------------------------------------------------
__global__ void k_stats()
{
    const int c = blockIdx.x * 128 + threadIdx.x;
    const int b = blockIdx.y;
    const int z = blockIdx.z;
    const float* src = z ? g_k : g_q;
    const float* p = src + (size_t)b * SS * CC + c;

    float s0 = 0, s1 = 0, s2 = 0, s3 = 0;
    float q0 = 0, q1 = 0, q2 = 0, q3 = 0;
    for (int s = 0; s < SS; s += 4) {
        float x0 = p[(size_t)(s + 0) * CC];
        float x1 = p[(size_t)(s + 1) * CC];
        float x2 = p[(size_t)(s + 2) * CC];
        float x3 = p[(size_t)(s + 3) * CC];
        s0 += x0; q0 = fmaf(x0, x0, q0);
        s1 += x1; q1 = fmaf(x1, x1, q1);
        s2 += x2; q2 = fmaf(x2, x2, q2);
        s3 += x3; q3 = fmaf(x3, x3, q3);
    }
    float sum = (s0 + s1) + (s2 + s3);
    float sq  = (q0 + q1) + (q2 + q3);
    float mean = sum * (1.0f / SS);
    float var  = (sq - sum * mean) * (1.0f / (SS - 1));
    float sd   = sqrtf(var + EPSV);
    g_mean[(z * BB + b) * CC + c] = mean;
    g_std [(z * BB + b) * CC + c] = sd;
}

__global__ void k_finalize()
{
    int i = blockIdx.x * 256 + threadIdx.x;   // (z*BB+b)*CC + c
    if (i >= 2 * BB * CC) return;
    int c  = i % CC;
    int b  = (i / CC) % BB;
    int z  = i / (CC * BB);
    int sb = (b < BB / 2) ? 0 : BB / 2;
    float sd  = g_std [(z * BB + b)  * CC + c];
    float sds = g_std [(z * BB + sb) * CC + c];
    float mn  = g_mean[(z * BB + b)  * CC + c];
    float mns = g_mean[(z * BB + sb) * CC + c];
    float scl = sds / sd;
    g_scl[i] = scl;
    g_shf[i] = mns - mn * scl;
}

__global__ void k_apply()
{
    const int TOT4  = 2 * BB * SS * CC / 4;
    const int per_t = SS * CC / 4;           // float4s per (z,b)
    int i4 = blockIdx.x * 256 + threadIdx.x;
    if (i4 >= TOT4) return;
    int zb = i4 / per_t;                     // 0..7 : z*BB + b
    int r  = i4 % per_t;
    int c  = (r % (CC / 4)) * 4;
    float* buf = (zb < BB) ? g_q : g_k;
    int b = zb & 3;
    float4* p = (float4*)buf + (size_t)b * per_t + r;
    float4 scl = *(const float4*)&g_scl[zb * CC + c];
    float4 shf = *(const float4*)&g_shf[zb * CC + c];
    float4 x = *p;
    x.x = fmaf(x.x, scl.x, shf.x);
    x.y = fmaf(x.y, scl.y, shf.y);
    x.z = fmaf(x.z, scl.z, shf.z);
    x.w = fmaf(x.w, scl.w, shf.w);
    *p = x;
}

// ---------------------------------------------------------------------------
// Flash attention, fp32. Block: 64 queries of one (b,h); keys = virtual
// concat [K[b]; K[style(b)]] (2048 rows), +log(2) bias on the style half.
// 256 threads as 16(ty: q) x 16(tx: k/n), 4x4 register tiles.
// smem pitch 68 floats: aligned float4 reads, conflict-free on hot path.
// ---------------------------------------------------------------------------
#define AP 68
#define ATT_SMEM (4 * 64 * AP * 4)

__global__ __launch_bounds__(256) void k_attn()
{
    extern __shared__ float sm[];
    float* Qs = sm;                // [d][q]  64 x AP
    float* Ks = Qs + 64 * AP;      // [d][k]
    float* Vs = Ks + 64 * AP;      // [k][n]
    float* Ps = Vs + 64 * AP;      // [k][q]

    const int tid = threadIdx.x;
    const int tx  = tid & 15;
    const int ty  = tid >> 4;
    const int bh  = blockIdx.y;
    const int b   = bh / HH;
    const int h   = bh % HH;
    const int q0  = blockIdx.x * 64;
    const int sb  = (b < BB / 2) ? 0 : BB / 2;

    // load Q tile, transposed to [d][q]
    {
        const float* Qg = g_q + (size_t)(b * SS + q0) * CC + h * DD;
#pragma unroll
        for (int i = 0; i < 4; i++) {
            int fid = tid + i * 256;
            int row = fid >> 4, c4 = fid & 15;
            float4 v = *(const float4*)(Qg + (size_t)row * CC + c4 * 4);
            int d = c4 * 4;
            Qs[(d + 0) * AP + row] = v.x;
            Qs[(d + 1) * AP + row] = v.y;
            Qs[(d + 2) * AP + row] = v.z;
            Qs[(d + 3) * AP + row] = v.w;
        }
    }

    float m[4], l[4], O[4][4];
#pragma unroll
    for (int j = 0; j < 4; j++) {
        m[j] = -1e30f; l[j] = 0.f;
#pragma unroll
        for (int i = 0; i < 4; i++) O[j][i] = 0.f;
    }

    for (int ch = 0; ch < 32; ch++) {
        int kb, kr0;
        float bias;
        if (ch < 16) { kb = b;  kr0 = ch * 64;        bias = 0.f;    }
        else         { kb = sb; kr0 = (ch - 16) * 64; bias = SHIFTV; }
        const float* Kg = g_k + (size_t)(kb * SS + kr0) * CC + h * DD;
        const float* Vg = g_v + (size_t)(kb * SS + kr0) * CC + h * DD;

        __syncthreads();   // previous iteration's PV reads are done
#pragma unroll
        for (int i = 0; i < 4; i++) {
            int fid = tid + i * 256;
            int row = fid >> 4, c4 = fid & 15;
            int d = c4 * 4;
            float4 kv = *(const float4*)(Kg + (size_t)row * CC + c4 * 4);
            Ks[(d + 0) * AP + row] = kv.x;
            Ks[(d + 1) * AP + row] = kv.y;
            Ks[(d + 2) * AP + row] = kv.z;
            Ks[(d + 3) * AP + row] = kv.w;
            float4 vv = *(const float4*)(Vg + (size_t)row * CC + c4 * 4);
            *(float4*)(Vs + row * AP + d) = vv;
        }
        __syncthreads();

        // S tile = Q^T-tile @ K-tile  (outer product over d)
        float s[4][4];
#pragma unroll
        for (int j = 0; j < 4; j++)
#pragma unroll
            for (int i = 0; i < 4; i++) s[j][i] = 0.f;

#pragma unroll 8
        for (int d = 0; d < 64; d++) {
            float4 a4 = *(const float4*)(Qs + d * AP + ty * 4);
            float4 b4 = *(const float4*)(Ks + d * AP + tx * 4);
            float aa[4] = {a4.x, a4.y, a4.z, a4.w};
            float bb[4] = {b4.x, b4.y, b4.z, b4.w};
#pragma unroll
            for (int j = 0; j < 4; j++)
#pragma unroll
                for (int i = 0; i < 4; i++)
                    s[j][i] = fmaf(aa[j], bb[i], s[j][i]);
        }

        // online softmax update
#pragma unroll
        for (int j = 0; j < 4; j++) {
#pragma unroll
            for (int i = 0; i < 4; i++) s[j][i] = fmaf(s[j][i], ATT_SCALE, bias);
            float mx = fmaxf(fmaxf(s[j][0], s[j][1]), fmaxf(s[j][2], s[j][3]));
            mx = fmaxf(mx, __shfl_xor_sync(0xffffffffu, mx, 1));
            mx = fmaxf(mx, __shfl_xor_sync(0xffffffffu, mx, 2));
            mx = fmaxf(mx, __shfl_xor_sync(0xffffffffu, mx, 4));
            mx = fmaxf(mx, __shfl_xor_sync(0xffffffffu, mx, 8));
            float mnew = fmaxf(m[j], mx);
            float al = __expf(m[j] - mnew);
            float rs = 0.f;
#pragma unroll
            for (int i = 0; i < 4; i++) {
                s[j][i] = __expf(s[j][i] - mnew);
                rs += s[j][i];
            }
            rs += __shfl_xor_sync(0xffffffffu, rs, 1);
            rs += __shfl_xor_sync(0xffffffffu, rs, 2);
            rs += __shfl_xor_sync(0xffffffffu, rs, 4);
            rs += __shfl_xor_sync(0xffffffffu, rs, 8);
            l[j] = l[j] * al + rs;
            m[j] = mnew;
#pragma unroll
            for (int i = 0; i < 4; i++) O[j][i] *= al;
        }

        // P -> smem (transposed to [k][q])
#pragma unroll
        for (int j = 0; j < 4; j++)
#pragma unroll
            for (int i = 0; i < 4; i++)
                Ps[(tx * 4 + i) * AP + ty * 4 + j] = s[j][i];
        __syncthreads();

        // O += P @ V  (outer product over k)
#pragma unroll 8
        for (int k = 0; k < 64; k++) {
            float4 p4 = *(const float4*)(Ps + k * AP + ty * 4);
            float4 v4 = *(const float4*)(Vs + k * AP + tx * 4);
            float pa[4] = {p4.x, p4.y, p4.z, p4.w};
            float vb[4] = {v4.x, v4.y, v4.z, v4.w};
#pragma unroll
            for (int j = 0; j < 4; j++)
#pragma unroll
                for (int i = 0; i < 4; i++)
                    O[j][i] = fmaf(pa[j], vb[i], O[j][i]);
        }
    }

    // epilogue: normalize and store
    float* Og = g_attn + (size_t)(b * SS + q0) * CC + h * DD;
#pragma unroll
    for (int j = 0; j < 4; j++) {
        float inv = 1.0f / l[j];
        float4 o = make_float4(O[j][0] * inv, O[j][1] * inv,
                               O[j][2] * inv, O[j][3] * inv);
        *(float4*)(Og + (size_t)(ty * 4 + j) * CC + tx * 4) = o;
    }
}

// ---------------------------------------------------------------------------
extern "C" void kernel_launch(void* const* d_in, const int* in_sizes, int n_in,
                              void* d_out, int out_size)
{
    (void)in_sizes; (void)n_in; (void)out_size;
    const float* X  = (const float*)d_in[0];
    const float* Wq = (const float*)d_in[1];
    const float* Wk = (const float*)d_in[2];
    const float* Wv = (const float*)d_in[3];
    const float* Wo = (const float*)d_in[4];
    const float* bo = (const float*)d_in[5];
    float* out = (float*)d_out;

    cudaFuncSetAttribute(k_attn, cudaFuncAttributeMaxDynamicSharedMemorySize,
                         ATT_SMEM);

    k_qkv<<<dim3(CC / 128, (BB * SS) / 128, 3), 256>>>(X, Wq, Wk, Wv);
    k_stats<<<dim3(CC / 128, BB, 2), 128>>>();
    k_finalize<<<(2 * BB * CC + 255) / 256, 256>>>();
    k_apply<<<(2 * BB * SS * CC / 4 + 255) / 256, 256>>>();
    k_attn<<<dim3(SS / 64, BB * HH), 256, ATT_SMEM>>>();
    k_proj_out<<<dim3(CC / 128, (BB * SS) / 128), 256>>>(Wo, bo, out);
}

// round 4
// speedup vs baseline: 1.4248x; 1.4248x over previous
#include <cuda_runtime.h>
#include <cstdint>
#include <math.h>

// Problem constants
#define BB 4
#define SS 1024
#define CC 1280
#define HH 20
#define DD 64
#define ATT_SCALE 0.125f              // 64^-0.5
#define SHIFTV 0.6931471805599453f    // log(2)
#define EPSV 1e-5f

// ---------------- scratch (static device allocations are allowed) -----------
__device__ float g_q[BB*SS*CC];
__device__ float g_k[BB*SS*CC];
__device__ float g_v[BB*SS*CC];
__device__ float g_attn[BB*SS*CC];
__device__ float g_mean[2*BB*CC];
__device__ float g_std[2*BB*CC];
__device__ float g_scl[2*BB*CC];
__device__ float g_shf[2*BB*CC];

// =================== mma.sync tf32 helpers (sm_80+ PTX, base-target safe) ===
__device__ __forceinline__ uint32_t f2tf32(float x) {
    uint32_t r;
    asm("cvt.rna.tf32.f32 %0, %1;" : "=r"(r) : "f"(x));
    return r;
}

__device__ __forceinline__ void mma_1688(
    float c[4], const uint32_t a[4], uint32_t b0, uint32_t b1)
{
    asm volatile(
        "mma.sync.aligned.m16n8k8.row.col.f32.tf32.tf32.f32 "
        "{%0,%1,%2,%3}, {%4,%5,%6,%7}, {%8,%9}, {%0,%1,%2,%3};\n"
        : "+f"(c[0]), "+f"(c[1]), "+f"(c[2]), "+f"(c[3])
        : "r"(a[0]), "r"(a[1]), "r"(a[2]), "r"(a[3]), "r"(b0), "r"(b1));
}

// ---------------------------------------------------------------------------
// Tensor-core tf32 GEMM: C[m][n] = sum_k A[m][k] * W[n][k] (+bias[n])
// Block 128x128, BK=16, 256 threads / 8 warps (4m x 2n), warp tile 32x64.
// Smem pitch 20 words -> fragment loads hit all 32 banks (conflict-free).
// ---------------------------------------------------------------------------
#define BKP 20
#define GKT (CC / 16)   // 80 k-tiles

__device__ __forceinline__ void gemm_mma_body(
    const float* __restrict__ A, const float* __restrict__ W,
    const float* __restrict__ bias, float* __restrict__ Cout)
{
    __shared__ uint32_t As[2][128 * BKP];
    __shared__ uint32_t Bs[2][128 * BKP];

    const int tid  = threadIdx.x;
    const int warp = tid >> 5, lane = tid & 31;
    const int wm   = (warp & 3) * 32;         // warp row offset in block tile
    const int wn   = (warp >> 2) * 64;        // warp col offset
    const int tg   = lane & 3, gid = lane >> 2;
    const int m0   = blockIdx.y * 128;
    const int n0   = blockIdx.x * 128;

    // gmem staging: 2 threads per row, 8 floats each
    const int lrow = tid >> 1;
    const int lc   = (tid & 1) * 8;
    const float* Ap = A + (size_t)(m0 + lrow) * CC + lc;
    const float* Bp = W + (size_t)(n0 + lrow) * CC + lc;

    float4 ra0 = *(const float4*)(Ap);
    float4 ra1 = *(const float4*)(Ap + 4);
    float4 rb0 = *(const float4*)(Bp);
    float4 rb1 = *(const float4*)(Bp + 4);

    float acc[2][8][4];
#pragma unroll
    for (int im = 0; im < 2; im++)
#pragma unroll
        for (int in_ = 0; in_ < 8; in_++)
#pragma unroll
            for (int r = 0; r < 4; r++) acc[im][in_][r] = 0.f;

    // store tile 0
    {
        uint32_t* sa = &As[0][lrow * BKP + lc];
        uint32_t* sb = &Bs[0][lrow * BKP + lc];
        uint4 t0 = make_uint4(f2tf32(ra0.x), f2tf32(ra0.y), f2tf32(ra0.z), f2tf32(ra0.w));
        uint4 t1 = make_uint4(f2tf32(ra1.x), f2tf32(ra1.y), f2tf32(ra1.z), f2tf32(ra1.w));
        *(uint4*)sa = t0; *(uint4*)(sa + 4) = t1;
        t0 = make_uint4(f2tf32(rb0.x), f2tf32(rb0.y), f2tf32(rb0.z), f2tf32(rb0.w));
        t1 = make_uint4(f2tf32(rb1.x), f2tf32(rb1.y), f2tf32(rb1.z), f2tf32(rb1.w));
        *(uint4*)sb = t0; *(uint4*)(sb + 4) = t1;
    }
    __syncthreads();

    for (int kt = 0; kt < GKT; kt++) {
        // prefetch next k-tile while computing this one
        if (kt + 1 < GKT) {
            const float* Ap2 = Ap + (kt + 1) * 16;
            const float* Bp2 = Bp + (kt + 1) * 16;
            ra0 = *(const float4*)(Ap2);
            ra1 = *(const float4*)(Ap2 + 4);
            rb0 = *(const float4*)(Bp2);
            rb1 = *(const float4*)(Bp2 + 4);
        }

        const uint32_t* sa = As[kt & 1];
        const uint32_t* sb = Bs[kt & 1];
#pragma unroll
        for (int ks = 0; ks < 16; ks += 8) {
            uint32_t af[2][4];
#pragma unroll
            for (int im = 0; im < 2; im++) {
                int r = wm + im * 16 + gid;
                af[im][0] = sa[(r + 0) * BKP + ks + tg];
                af[im][1] = sa[(r + 8) * BKP + ks + tg];
                af[im][2] = sa[(r + 0) * BKP + ks + tg + 4];
                af[im][3] = sa[(r + 8) * BKP + ks + tg + 4];
            }
#pragma unroll
            for (int in_ = 0; in_ < 8; in_++) {
                int n = wn + in_ * 8 + gid;
                uint32_t b0 = sb[n * BKP + ks + tg];
                uint32_t b1 = sb[n * BKP + ks + tg + 4];
                mma_1688(acc[0][in_], af[0], b0, b1);
                mma_1688(acc[1][in_], af[1], b0, b1);
            }
        }

        if (kt + 1 < GKT) {
            __syncthreads();   // everyone done reading buf (kt+1)&1 from iter kt-1
            uint32_t* da = &As[(kt + 1) & 1][lrow * BKP + lc];
            uint32_t* db = &Bs[(kt + 1) & 1][lrow * BKP + lc];
            uint4 t0 = make_uint4(f2tf32(ra0.x), f2tf32(ra0.y), f2tf32(ra0.z), f2tf32(ra0.w));
            uint4 t1 = make_uint4(f2tf32(ra1.x), f2tf32(ra1.y), f2tf32(ra1.z), f2tf32(ra1.w));
            *(uint4*)da = t0; *(uint4*)(da + 4) = t1;
            t0 = make_uint4(f2tf32(rb0.x), f2tf32(rb0.y), f2tf32(rb0.z), f2tf32(rb0.w));
            t1 = make_uint4(f2tf32(rb1.x), f2tf32(rb1.y), f2tf32(rb1.z), f2tf32(rb1.w));
            *(uint4*)db = t0; *(uint4*)(db + 4) = t1;
            __syncthreads();
        }
    }

    // epilogue: c0: (gid, tg*2), c1: col+1, c2/c3: row+8
#pragma unroll
    for (int im = 0; im < 2; im++) {
        int row = m0 + wm + im * 16 + gid;
#pragma unroll
        for (int in_ = 0; in_ < 8; in_++) {
            int col = n0 + wn + in_ * 8 + tg * 2;
            float b0v = 0.f, b1v = 0.f;
            if (bias) { b0v = bias[col]; b1v = bias[col + 1]; }
            float2 lo = make_float2(acc[im][in_][0] + b0v, acc[im][in_][1] + b1v);
            float2 hi = make_float2(acc[im][in_][2] + b0v, acc[im][in_][3] + b1v);
            *(float2*)(Cout + (size_t)row * CC + col)       = lo;
            *(float2*)(Cout + (size_t)(row + 8) * CC + col) = hi;
        }
    }
}

__global__ __launch_bounds__(256) void k_qkv_mma(
    const float* __restrict__ X, const float* __restrict__ Wq,
    const float* __restrict__ Wk, const float* __restrict__ Wv)
{
    const float* W;
    float* O;
    if (blockIdx.z == 0)      { W = Wq; O = g_q; }
    else if (blockIdx.z == 1) { W = Wk; O = g_k; }
    else                      { W = Wv; O = g_v; }
    gemm_mma_body(X, W, nullptr, O);
}

__global__ __launch_bounds__(256) void k_proj_mma(
    const float* __restrict__ Wo, const float* __restrict__ bo,
    float* __restrict__ out)
{
    gemm_mma_body(g_attn, Wo, bo, out);
}

// ---------------------------------------------------------------------------
// AdaIN: stats over sequence axis (unbiased var), per (tensor z, batch b, ch c)
// ---------------------------------------------------------------------------
__global__ void k_stats()
{
    const int c = blockIdx.x * 128 + threadIdx.x;
    const int b = blockIdx.y;
    const int z = blockIdx.z;
    const float* src = z ? g_k : g_q;
    const float* p = src + (size_t)b * SS * CC + c;

    float s0 = 0, s1 = 0, s2 = 0, s3 = 0;
    float q0 = 0, q1 = 0, q2 = 0, q3 = 0;
    for (int s = 0; s < SS; s += 4) {
        float x0 = p[(size_t)(s + 0) * CC];
        float x1 = p[(size_t)(s + 1) * CC];
        float x2 = p[(size_t)(s + 2) * CC];
        float x3 = p[(size_t)(s + 3) * CC];
        s0 += x0; q0 = fmaf(x0, x0, q0);
        s1 += x1; q1 = fmaf(x1, x1, q1);
        s2 += x2; q2 = fmaf(x2, x2, q2);
        s3 += x3; q3 = fmaf(x3, x3, q3);
    }
    float sum = (s0 + s1) + (s2 + s3);
    float sq  = (q0 + q1) + (q2 + q3);
    float mean = sum * (1.0f / SS);
    float var  = (sq - sum * mean) * (1.0f / (SS - 1));
    float sd   = sqrtf(var + EPSV);
    g_mean[(z * BB + b) * CC + c] = mean;
    g_std [(z * BB + b) * CC + c] = sd;
}

__global__ void k_finalize()
{
    int i = blockIdx.x * 256 + threadIdx.x;   // (z*BB+b)*CC + c
    if (i >= 2 * BB * CC) return;
    int c  = i % CC;
    int b  = (i / CC) % BB;
    int z  = i / (CC * BB);
    int sb = (b < BB / 2) ? 0 : BB / 2;
    float sd  = g_std [(z * BB + b)  * CC + c];
    float sds = g_std [(z * BB + sb) * CC + c];
    float mn  = g_mean[(z * BB + b)  * CC + c];
    float mns = g_mean[(z * BB + sb) * CC + c];
    float scl = sds / sd;
    g_scl[i] = scl;
    g_shf[i] = mns - mn * scl;
}

__global__ void k_apply()
{
    const int TOT4  = 2 * BB * SS * CC / 4;
    const int per_t = SS * CC / 4;           // float4s per (z,b)
    int i4 = blockIdx.x * 256 + threadIdx.x;
    if (i4 >= TOT4) return;
    int zb = i4 / per_t;                     // 0..7 : z*BB + b
    int r  = i4 % per_t;
    int c  = (r % (CC / 4)) * 4;
    float* buf = (zb < BB) ? g_q : g_k;
    int b = zb & 3;
    float4* p = (float4*)buf + (size_t)b * per_t + r;
    float4 scl = *(const float4*)&g_scl[zb * CC + c];
    float4 shf = *(const float4*)&g_shf[zb * CC + c];
    float4 x = *p;
    x.x = fmaf(x.x, scl.x, shf.x);
    x.y = fmaf(x.y, scl.y, shf.y);
    x.z = fmaf(x.z, scl.z, shf.z);
    x.w = fmaf(x.w, scl.w, shf.w);
    *p = x;
}

// ---------------------------------------------------------------------------
// Flash attention, fp32. Block: 64 queries of one (b,h); keys = virtual
// concat [K[b]; K[style(b)]] (2048 rows), +log(2) bias on the style half.
// 256 threads as 16(ty: q) x 16(tx: k/n), 4x4 register tiles.
// ---------------------------------------------------------------------------
#define AP 68
#define ATT_SMEM (4 * 64 * AP * 4)

__global__ __launch_bounds__(256) void k_attn()
{
    extern __shared__ float sm[];
    float* Qs = sm;                // [d][q]  64 x AP
    float* Ks = Qs + 64 * AP;      // [d][k]
    float* Vs = Ks + 64 * AP;      // [k][n]
    float* Ps = Vs + 64 * AP;      // [k][q]

    const int tid = threadIdx.x;
    const int tx  = tid & 15;
    const int ty  = tid >> 4;
    const int bh  = blockIdx.y;
    const int b   = bh / HH;
    const int h   = bh % HH;
    const int q0  = blockIdx.x * 64;
    const int sb  = (b < BB / 2) ? 0 : BB / 2;

    // load Q tile, transposed to [d][q]
    {
        const float* Qg = g_q + (size_t)(b * SS + q0) * CC + h * DD;
#pragma unroll
        for (int i = 0; i < 4; i++) {
            int fid = tid + i * 256;
            int row = fid >> 4, c4 = fid & 15;
            float4 v = *(const float4*)(Qg + (size_t)row * CC + c4 * 4);
            int d = c4 * 4;
            Qs[(d + 0) * AP + row] = v.x;
            Qs[(d + 1) * AP + row] = v.y;
            Qs[(d + 2) * AP + row] = v.z;
            Qs[(d + 3) * AP + row] = v.w;
        }
    }

    float m[4], l[4], O[4][4];
#pragma unroll
    for (int j = 0; j < 4; j++) {
        m[j] = -1e30f; l[j] = 0.f;
#pragma unroll
        for (int i = 0; i < 4; i++) O[j][i] = 0.f;
    }

    for (int ch = 0; ch < 32; ch++) {
        int kb, kr0;
        float bias;
        if (ch < 16) { kb = b;  kr0 = ch * 64;        bias = 0.f;    }
        else         { kb = sb; kr0 = (ch - 16) * 64; bias = SHIFTV; }
        const float* Kg = g_k + (size_t)(kb * SS + kr0) * CC + h * DD;
        const float* Vg = g_v + (size_t)(kb * SS + kr0) * CC + h * DD;

        __syncthreads();   // previous iteration's PV reads are done
#pragma unroll
        for (int i = 0; i < 4; i++) {
            int fid = tid + i * 256;
            int row = fid >> 4, c4 = fid & 15;
            int d = c4 * 4;
            float4 kv = *(const float4*)(Kg + (size_t)row * CC + c4 * 4);
            Ks[(d + 0) * AP + row] = kv.x;
            Ks[(d + 1) * AP + row] = kv.y;
            Ks[(d + 2) * AP + row] = kv.z;
            Ks[(d + 3) * AP + row] = kv.w;
            float4 vv = *(const float4*)(Vg + (size_t)row * CC + c4 * 4);
            *(float4*)(Vs + row * AP + d) = vv;
        }
        __syncthreads();

        // S tile = Q^T-tile @ K-tile  (outer product over d)
        float s[4][4];
#pragma unroll
        for (int j = 0; j < 4; j++)
#pragma unroll
            for (int i = 0; i < 4; i++) s[j][i] = 0.f;

#pragma unroll 8
        for (int d = 0; d < 64; d++) {
            float4 a4 = *(const float4*)(Qs + d * AP + ty * 4);
            float4 b4 = *(const float4*)(Ks + d * AP + tx * 4);
            float aa[4] = {a4.x, a4.y, a4.z, a4.w};
            float bb[4] = {b4.x, b4.y, b4.z, b4.w};
#pragma unroll
            for (int j = 0; j < 4; j++)
#pragma unroll
                for (int i = 0; i < 4; i++)
                    s[j][i] = fmaf(aa[j], bb[i], s[j][i]);
        }

        // online softmax update
#pragma unroll
        for (int j = 0; j < 4; j++) {
#pragma unroll
            for (int i = 0; i < 4; i++) s[j][i] = fmaf(s[j][i], ATT_SCALE, bias);
            float mx = fmaxf(fmaxf(s[j][0], s[j][1]), fmaxf(s[j][2], s[j][3]));
            mx = fmaxf(mx, __shfl_xor_sync(0xffffffffu, mx, 1));
            mx = fmaxf(mx, __shfl_xor_sync(0xffffffffu, mx, 2));
            mx = fmaxf(mx, __shfl_xor_sync(0xffffffffu, mx, 4));
            mx = fmaxf(mx, __shfl_xor_sync(0xffffffffu, mx, 8));
            float mnew = fmaxf(m[j], mx);
            float al = __expf(m[j] - mnew);
            float rs = 0.f;
#pragma unroll
            for (int i = 0; i < 4; i++) {
                s[j][i] = __expf(s[j][i] - mnew);
                rs += s[j][i];
            }
            rs += __shfl_xor_sync(0xffffffffu, rs, 1);
            rs += __shfl_xor_sync(0xffffffffu, rs, 2);
            rs += __shfl_xor_sync(0xffffffffu, rs, 4);
            rs += __shfl_xor_sync(0xffffffffu, rs, 8);
            l[j] = l[j] * al + rs;
            m[j] = mnew;
#pragma unroll
            for (int i = 0; i < 4; i++) O[j][i] *= al;
        }

        // P -> smem (transposed to [k][q])
#pragma unroll
        for (int j = 0; j < 4; j++)
#pragma unroll
            for (int i = 0; i < 4; i++)
                Ps[(tx * 4 + i) * AP + ty * 4 + j] = s[j][i];
        __syncthreads();

        // O += P @ V  (outer product over k)
#pragma unroll 8
        for (int k = 0; k < 64; k++) {
            float4 p4 = *(const float4*)(Ps + k * AP + ty * 4);
            float4 v4 = *(const float4*)(Vs + k * AP + tx * 4);
            float pa[4] = {p4.x, p4.y, p4.z, p4.w};
            float vb[4] = {v4.x, v4.y, v4.z, v4.w};
#pragma unroll
            for (int j = 0; j < 4; j++)
#pragma unroll
                for (int i = 0; i < 4; i++)
                    O[j][i] = fmaf(pa[j], vb[i], O[j][i]);
        }
    }

    // epilogue: normalize and store
    float* Og = g_attn + (size_t)(b * SS + q0) * CC + h * DD;
#pragma unroll
    for (int j = 0; j < 4; j++) {
        float inv = 1.0f / l[j];
        float4 o = make_float4(O[j][0] * inv, O[j][1] * inv,
                               O[j][2] * inv, O[j][3] * inv);
        *(float4*)(Og + (size_t)(ty * 4 + j) * CC + tx * 4) = o;
    }
}

// ---------------------------------------------------------------------------
extern "C" void kernel_launch(void* const* d_in, const int* in_sizes, int n_in,
                              void* d_out, int out_size)
{
    (void)in_sizes; (void)n_in; (void)out_size;
    const float* X  = (const float*)d_in[0];
    const float* Wq = (const float*)d_in[1];
    const float* Wk = (const float*)d_in[2];
    const float* Wv = (const float*)d_in[3];
    const float* Wo = (const float*)d_in[4];
    const float* bo = (const float*)d_in[5];
    float* out = (float*)d_out;

    cudaFuncSetAttribute(k_attn, cudaFuncAttributeMaxDynamicSharedMemorySize,
                         ATT_SMEM);

    k_qkv_mma<<<dim3(CC / 128, (BB * SS) / 128, 3), 256>>>(X, Wq, Wk, Wv);
    k_stats<<<dim3(CC / 128, BB, 2), 128>>>();
    k_finalize<<<(2 * BB * CC + 255) / 256, 256>>>();
    k_apply<<<(2 * BB * SS * CC / 4 + 255) / 256, 256>>>();
    k_attn<<<dim3(SS / 64, BB * HH), 256, ATT_SMEM>>>();
    k_proj_mma<<<dim3(CC / 128, (BB * SS) / 128), 256>>>(Wo, bo, out);
}

// round 5
// speedup vs baseline: 2.6407x; 1.8534x over previous
#include <cuda_runtime.h>
#include <cstdint>
#include <math.h>

// Problem constants
#define BB 4
#define SS 1024
#define CC 1280
#define HH 20
#define DD 64
#define ATT_SCALE 0.125f              // 64^-0.5
#define SHIFTV 0.6931471805599453f    // log(2)
#define EPSV 1e-5f

// ---------------- scratch (static device allocations are allowed) -----------
__device__ float g_q[BB*SS*CC];
__device__ float g_k[BB*SS*CC];
__device__ float g_v[BB*SS*CC];
__device__ float g_vt[BB*SS*CC];      // V transposed: [b][h][d][s]
__device__ float g_attn[BB*SS*CC];
__device__ float g_mean[2*BB*CC];
__device__ float g_std[2*BB*CC];
__device__ float g_scl[2*BB*CC];
__device__ float g_shf[2*BB*CC];

// =================== mma.sync tf32 helpers (sm_80+ PTX, base-target safe) ===
__device__ __forceinline__ uint32_t f2tf32(float x) {
    uint32_t r;
    asm("cvt.rna.tf32.f32 %0, %1;" : "=r"(r) : "f"(x));
    return r;
}

__device__ __forceinline__ void mma_1688(
    float c[4], const uint32_t a[4], uint32_t b0, uint32_t b1)
{
    asm volatile(
        "mma.sync.aligned.m16n8k8.row.col.f32.tf32.tf32.f32 "
        "{%0,%1,%2,%3}, {%4,%5,%6,%7}, {%8,%9}, {%0,%1,%2,%3};\n"
        : "+f"(c[0]), "+f"(c[1]), "+f"(c[2]), "+f"(c[3])
        : "r"(a[0]), "r"(a[1]), "r"(a[2]), "r"(a[3]), "r"(b0), "r"(b1));
}

// ---------------------------------------------------------------------------
// Tensor-core tf32 GEMM: C[m][n] = sum_k A[m][k] * W[n][k] (+bias[n])
// Block 128x128, BK=16, 256 threads / 8 warps (4m x 2n), warp tile 32x64.
// ---------------------------------------------------------------------------
#define BKP 20
#define GKT (CC / 16)   // 80 k-tiles

__device__ __forceinline__ void gemm_mma_body(
    const float* __restrict__ A, const float* __restrict__ W,
    const float* __restrict__ bias, float* __restrict__ Cout)
{
    __shared__ uint32_t As[2][128 * BKP];
    __shared__ uint32_t Bs[2][128 * BKP];

    const int tid  = threadIdx.x;
    const int warp = tid >> 5, lane = tid & 31;
    const int wm   = (warp & 3) * 32;
    const int wn   = (warp >> 2) * 64;
    const int tg   = lane & 3, gid = lane >> 2;
    const int m0   = blockIdx.y * 128;
    const int n0   = blockIdx.x * 128;

    const int lrow = tid >> 1;
    const int lc   = (tid & 1) * 8;
    const float* Ap = A + (size_t)(m0 + lrow) * CC + lc;
    const float* Bp = W + (size_t)(n0 + lrow) * CC + lc;

    float4 ra0 = *(const float4*)(Ap);
    float4 ra1 = *(const float4*)(Ap + 4);
    float4 rb0 = *(const float4*)(Bp);
    float4 rb1 = *(const float4*)(Bp + 4);

    float acc[2][8][4];
#pragma unroll
    for (int im = 0; im < 2; im++)
#pragma unroll
        for (int in_ = 0; in_ < 8; in_++)
#pragma unroll
            for (int r = 0; r < 4; r++) acc[im][in_][r] = 0.f;

    {
        uint32_t* sa = &As[0][lrow * BKP + lc];
        uint32_t* sb = &Bs[0][lrow * BKP + lc];
        uint4 t0 = make_uint4(f2tf32(ra0.x), f2tf32(ra0.y), f2tf32(ra0.z), f2tf32(ra0.w));
        uint4 t1 = make_uint4(f2tf32(ra1.x), f2tf32(ra1.y), f2tf32(ra1.z), f2tf32(ra1.w));
        *(uint4*)sa = t0; *(uint4*)(sa + 4) = t1;
        t0 = make_uint4(f2tf32(rb0.x), f2tf32(rb0.y), f2tf32(rb0.z), f2tf32(rb0.w));
        t1 = make_uint4(f2tf32(rb1.x), f2tf32(rb1.y), f2tf32(rb1.z), f2tf32(rb1.w));
        *(uint4*)sb = t0; *(uint4*)(sb + 4) = t1;
    }
    __syncthreads();

    for (int kt = 0; kt < GKT; kt++) {
        if (kt + 1 < GKT) {
            const float* Ap2 = Ap + (kt + 1) * 16;
            const float* Bp2 = Bp + (kt + 1) * 16;
            ra0 = *(const float4*)(Ap2);
            ra1 = *(const float4*)(Ap2 + 4);
            rb0 = *(const float4*)(Bp2);
            rb1 = *(const float4*)(Bp2 + 4);
        }

        const uint32_t* sa = As[kt & 1];
        const uint32_t* sb = Bs[kt & 1];
#pragma unroll
        for (int ks = 0; ks < 16; ks += 8) {
            uint32_t af[2][4];
#pragma unroll
            for (int im = 0; im < 2; im++) {
                int r = wm + im * 16 + gid;
                af[im][0] = sa[(r + 0) * BKP + ks + tg];
                af[im][1] = sa[(r + 8) * BKP + ks + tg];
                af[im][2] = sa[(r + 0) * BKP + ks + tg + 4];
                af[im][3] = sa[(r + 8) * BKP + ks + tg + 4];
            }
#pragma unroll
            for (int in_ = 0; in_ < 8; in_++) {
                int n = wn + in_ * 8 + gid;
                uint32_t b0 = sb[n * BKP + ks + tg];
                uint32_t b1 = sb[n * BKP + ks + tg + 4];
                mma_1688(acc[0][in_], af[0], b0, b1);
                mma_1688(acc[1][in_], af[1], b0, b1);
            }
        }

        if (kt + 1 < GKT) {
            __syncthreads();
            uint32_t* da = &As[(kt + 1) & 1][lrow * BKP + lc];
            uint32_t* db = &Bs[(kt + 1) & 1][lrow * BKP + lc];
            uint4 t0 = make_uint4(f2tf32(ra0.x), f2tf32(ra0.y), f2tf32(ra0.z), f2tf32(ra0.w));
            uint4 t1 = make_uint4(f2tf32(ra1.x), f2tf32(ra1.y), f2tf32(ra1.z), f2tf32(ra1.w));
            *(uint4*)da = t0; *(uint4*)(da + 4) = t1;
            t0 = make_uint4(f2tf32(rb0.x), f2tf32(rb0.y), f2tf32(rb0.z), f2tf32(rb0.w));
            t1 = make_uint4(f2tf32(rb1.x), f2tf32(rb1.y), f2tf32(rb1.z), f2tf32(rb1.w));
            *(uint4*)db = t0; *(uint4*)(db + 4) = t1;
            __syncthreads();
        }
    }

#pragma unroll
    for (int im = 0; im < 2; im++) {
        int row = m0 + wm + im * 16 + gid;
#pragma unroll
        for (int in_ = 0; in_ < 8; in_++) {
            int col = n0 + wn + in_ * 8 + tg * 2;
            float b0v = 0.f, b1v = 0.f;
            if (bias) { b0v = bias[col]; b1v = bias[col + 1]; }
            float2 lo = make_float2(acc[im][in_][0] + b0v, acc[im][in_][1] + b1v);
            float2 hi = make_float2(acc[im][in_][2] + b0v, acc[im][in_][3] + b1v);
            *(float2*)(Cout + (size_t)row * CC + col)       = lo;
            *(float2*)(Cout + (size_t)(row + 8) * CC + col) = hi;
        }
    }
}

__global__ __launch_bounds__(256) void k_qkv_mma(
    const float* __restrict__ X, const float* __restrict__ Wq,
    const float* __restrict__ Wk, const float* __restrict__ Wv)
{
    const float* W;
    float* O;
    if (blockIdx.z == 0)      { W = Wq; O = g_q; }
    else if (blockIdx.z == 1) { W = Wk; O = g_k; }
    else                      { W = Wv; O = g_v; }
    gemm_mma_body(X, W, nullptr, O);
}

__global__ __launch_bounds__(256) void k_proj_mma(
    const float* __restrict__ Wo, const float* __restrict__ bo,
    float* __restrict__ out)
{
    gemm_mma_body(g_attn, Wo, bo, out);
}

// ---------------------------------------------------------------------------
// V transpose: g_v [b][s][h][d]  ->  g_vt [b][h][d][s]
// 32x32 tiles, block 32x8.
// ---------------------------------------------------------------------------
__global__ __launch_bounds__(256) void k_transv()
{
    __shared__ float tile[32][33];
    const int bh = blockIdx.z;
    const int b  = bh / HH, h = bh % HH;
    const int s0 = blockIdx.x * 32;
    const int d0 = blockIdx.y * 32;
    const int tx = threadIdx.x, ty = threadIdx.y;

    const float* src = g_v + (size_t)(b * SS + s0) * CC + h * DD + d0;
#pragma unroll
    for (int j = 0; j < 32; j += 8)
        tile[ty + j][tx] = src[(size_t)(ty + j) * CC + tx];
    __syncthreads();

    float* dst = g_vt + ((size_t)(b * HH + h) * DD + d0) * SS + s0;
#pragma unroll
    for (int j = 0; j < 32; j += 8)
        dst[(size_t)(ty + j) * SS + tx] = tile[tx][ty + j];
}

// ---------------------------------------------------------------------------
// AdaIN stats / finalize / apply (unchanged)
// ---------------------------------------------------------------------------
__global__ void k_stats()
{
    const int c = blockIdx.x * 128 + threadIdx.x;
    const int b = blockIdx.y;
    const int z = blockIdx.z;
    const float* src = z ? g_k : g_q;
    const float* p = src + (size_t)b * SS * CC + c;

    float s0 = 0, s1 = 0, s2 = 0, s3 = 0;
    float q0 = 0, q1 = 0, q2 = 0, q3 = 0;
    for (int s = 0; s < SS; s += 4) {
        float x0 = p[(size_t)(s + 0) * CC];
        float x1 = p[(size_t)(s + 1) * CC];
        float x2 = p[(size_t)(s + 2) * CC];
        float x3 = p[(size_t)(s + 3) * CC];
        s0 += x0; q0 = fmaf(x0, x0, q0);
        s1 += x1; q1 = fmaf(x1, x1, q1);
        s2 += x2; q2 = fmaf(x2, x2, q2);
        s3 += x3; q3 = fmaf(x3, x3, q3);
    }
    float sum = (s0 + s1) + (s2 + s3);
    float sq  = (q0 + q1) + (q2 + q3);
    float mean = sum * (1.0f / SS);
    float var  = (sq - sum * mean) * (1.0f / (SS - 1));
    float sd   = sqrtf(var + EPSV);
    g_mean[(z * BB + b) * CC + c] = mean;
    g_std [(z * BB + b) * CC + c] = sd;
}

__global__ void k_finalize()
{
    int i = blockIdx.x * 256 + threadIdx.x;
    if (i >= 2 * BB * CC) return;
    int c  = i % CC;
    int b  = (i / CC) % BB;
    int z  = i / (CC * BB);
    int sb = (b < BB / 2) ? 0 : BB / 2;
    float sd  = g_std [(z * BB + b)  * CC + c];
    float sds = g_std [(z * BB + sb) * CC + c];
    float mn  = g_mean[(z * BB + b)  * CC + c];
    float mns = g_mean[(z * BB + sb) * CC + c];
    float scl = sds / sd;
    g_scl[i] = scl;
    g_shf[i] = mns - mn * scl;
}

__global__ void k_apply()
{
    const int TOT4  = 2 * BB * SS * CC / 4;
    const int per_t = SS * CC / 4;
    int i4 = blockIdx.x * 256 + threadIdx.x;
    if (i4 >= TOT4) return;
    int zb = i4 / per_t;
    int r  = i4 % per_t;
    int c  = (r % (CC / 4)) * 4;
    float* buf = (zb < BB) ? g_q : g_k;
    int b = zb & 3;
    float4* p = (float4*)buf + (size_t)b * per_t + r;
    float4 scl = *(const float4*)&g_scl[zb * CC + c];
    float4 shf = *(const float4*)&g_shf[zb * CC + c];
    float4 x = *p;
    x.x = fmaf(x.x, scl.x, shf.x);
    x.y = fmaf(x.y, scl.y, shf.y);
    x.z = fmaf(x.z, scl.z, shf.z);
    x.w = fmaf(x.w, scl.w, shf.w);
    *p = x;
}

// ---------------------------------------------------------------------------
// Flash attention on tensor cores (tf32 mma.sync).
// CTA: 128 queries of one (b,h). 8 warps x 16 q-rows. Chunks of 64 keys,
// 32 chunks (16 self + 16 style with +log2 bias). V comes pre-transposed
// (g_vt) so all smem stores/loads are conflict-free with pitch 68.
// P is re-laid-out through warp-private smem for the PV mma.
// ---------------------------------------------------------------------------
#define FP 68                       // smem pitch (words), 68 % 32 == 4
#define SM_K 0                      // Ks: 64 x FP
#define SM_V (64 * FP)              // Vt: 64 x FP
#define SM_P (128 * FP)             // Ps: 128 x FP (also Q staging)
#define ATT_SMEM ((128 * FP + 128 * FP) * 4)   // 69632 bytes

__global__ __launch_bounds__(256, 2) void k_attn_mma()
{
    extern __shared__ uint32_t sm[];
    uint32_t* Ks = sm + SM_K;
    uint32_t* Vt = sm + SM_V;
    uint32_t* Ps = sm + SM_P;       // per-warp 16-row slices; also Q staging

    const int tid  = threadIdx.x;
    const int warp = tid >> 5, lane = tid & 31;
    const int tg   = lane & 3, gid = lane >> 2;
    const int bh   = blockIdx.y;
    const int b    = bh / HH;
    const int h    = bh % HH;
    const int q0   = blockIdx.x * 128;
    const int sbv  = (b < BB / 2) ? 0 : BB / 2;
    const int wq   = warp * 16;

    // ---- stage Q tile (128 x 64) into Ps region as tf32, then grab frags ----
    {
        const float* Qg = g_q + (size_t)(b * SS + q0) * CC + h * DD;
#pragma unroll
        for (int i = 0; i < 8; i++) {
            int fid = tid + i * 256;
            int row = fid >> 4, c4 = fid & 15;
            float4 v = *(const float4*)(Qg + (size_t)row * CC + c4 * 4);
            uint4 t = make_uint4(f2tf32(v.x), f2tf32(v.y), f2tf32(v.z), f2tf32(v.w));
            *(uint4*)(Ps + row * FP + c4 * 4) = t;
        }
    }
    __syncthreads();

    uint32_t qf[8][4];
#pragma unroll
    for (int ks = 0; ks < 8; ks++) {
        qf[ks][0] = Ps[(wq + gid) * FP + ks * 8 + tg];
        qf[ks][1] = Ps[(wq + gid + 8) * FP + ks * 8 + tg];
        qf[ks][2] = Ps[(wq + gid) * FP + ks * 8 + tg + 4];
        qf[ks][3] = Ps[(wq + gid + 8) * FP + ks * 8 + tg + 4];
    }
    __syncthreads();   // Q staging reads done; Ps now free for P tiles

    float o[8][4];
#pragma unroll
    for (int n_ = 0; n_ < 8; n_++)
#pragma unroll
        for (int r = 0; r < 4; r++) o[n_][r] = 0.f;
    float m0r = -1e30f, m1r = -1e30f, l0r = 0.f, l1r = 0.f;

    for (int ch = 0; ch < 32; ch++) {
        const int  self = (ch < 16);
        const int  kb   = self ? b : sbv;
        const int  kr0  = (self ? ch : ch - 16) * 64;
        const float bias = self ? 0.f : SHIFTV;

        __syncthreads();   // previous chunk's mma reads of Ks/Vt done
        {
            const float* Kg = g_k + (size_t)(kb * SS + kr0) * CC + h * DD;
            const float* Vg = g_vt + ((size_t)(kb * HH + h) * DD) * SS + kr0;
#pragma unroll
            for (int i = 0; i < 4; i++) {
                int fid = tid + i * 256;
                int row = fid >> 4, c4 = fid & 15;
                float4 kv = *(const float4*)(Kg + (size_t)row * CC + c4 * 4);
                uint4 tk = make_uint4(f2tf32(kv.x), f2tf32(kv.y), f2tf32(kv.z), f2tf32(kv.w));
                *(uint4*)(Ks + row * FP + c4 * 4) = tk;
                float4 vv = *(const float4*)(Vg + (size_t)row * SS + c4 * 4);
                uint4 tv = make_uint4(f2tf32(vv.x), f2tf32(vv.y), f2tf32(vv.z), f2tf32(vv.w));
                *(uint4*)(Vt + row * FP + c4 * 4) = tv;
            }
        }
        __syncthreads();

        // ---- S = Q @ K^T  (16 x 64 per warp) ----
        float sacc[8][4];
#pragma unroll
        for (int n_ = 0; n_ < 8; n_++)
#pragma unroll
            for (int r = 0; r < 4; r++) sacc[n_][r] = 0.f;

#pragma unroll
        for (int ks = 0; ks < 8; ks++) {
#pragma unroll
            for (int n_ = 0; n_ < 8; n_++) {
                uint32_t b0 = Ks[(n_ * 8 + gid) * FP + ks * 8 + tg];
                uint32_t b1 = Ks[(n_ * 8 + gid) * FP + ks * 8 + tg + 4];
                mma_1688(sacc[n_], qf[ks], b0, b1);
            }
        }

        // ---- online softmax (rows gid -> c0/c1, gid+8 -> c2/c3) ----
        float mx0 = -1e30f, mx1 = -1e30f;
#pragma unroll
        for (int n_ = 0; n_ < 8; n_++) {
            sacc[n_][0] = fmaf(sacc[n_][0], ATT_SCALE, bias);
            sacc[n_][1] = fmaf(sacc[n_][1], ATT_SCALE, bias);
            sacc[n_][2] = fmaf(sacc[n_][2], ATT_SCALE, bias);
            sacc[n_][3] = fmaf(sacc[n_][3], ATT_SCALE, bias);
            mx0 = fmaxf(mx0, fmaxf(sacc[n_][0], sacc[n_][1]));
            mx1 = fmaxf(mx1, fmaxf(sacc[n_][2], sacc[n_][3]));
        }
        mx0 = fmaxf(mx0, __shfl_xor_sync(0xffffffffu, mx0, 1));
        mx0 = fmaxf(mx0, __shfl_xor_sync(0xffffffffu, mx0, 2));
        mx1 = fmaxf(mx1, __shfl_xor_sync(0xffffffffu, mx1, 1));
        mx1 = fmaxf(mx1, __shfl_xor_sync(0xffffffffu, mx1, 2));

        float mn0 = fmaxf(m0r, mx0), mn1 = fmaxf(m1r, mx1);
        float al0 = __expf(m0r - mn0), al1 = __expf(m1r - mn1);
        m0r = mn0; m1r = mn1;

        float rs0 = 0.f, rs1 = 0.f;
        const uint32_t pbase = wq * FP;
#pragma unroll
        for (int n_ = 0; n_ < 8; n_++) {
            float p0 = __expf(sacc[n_][0] - mn0);
            float p1 = __expf(sacc[n_][1] - mn0);
            float p2 = __expf(sacc[n_][2] - mn1);
            float p3 = __expf(sacc[n_][3] - mn1);
            rs0 += p0 + p1; rs1 += p2 + p3;
            uint2 lo = make_uint2(f2tf32(p0), f2tf32(p1));
            uint2 hi = make_uint2(f2tf32(p2), f2tf32(p3));
            *(uint2*)(Ps + pbase + gid * FP + n_ * 8 + tg * 2)       = lo;
            *(uint2*)(Ps + pbase + (gid + 8) * FP + n_ * 8 + tg * 2) = hi;
        }
        rs0 += __shfl_xor_sync(0xffffffffu, rs0, 1);
        rs0 += __shfl_xor_sync(0xffffffffu, rs0, 2);
        rs1 += __shfl_xor_sync(0xffffffffu, rs1, 1);
        rs1 += __shfl_xor_sync(0xffffffffu, rs1, 2);
        l0r = l0r * al0 + rs0;
        l1r = l1r * al1 + rs1;

#pragma unroll
        for (int n_ = 0; n_ < 8; n_++) {
            o[n_][0] *= al0; o[n_][1] *= al0;
            o[n_][2] *= al1; o[n_][3] *= al1;
        }
        __syncwarp();

        // ---- O += P @ V  (A = warp-private P, B = Vt) ----
#pragma unroll
        for (int ks = 0; ks < 8; ks++) {
            uint32_t pf[4];
            pf[0] = Ps[pbase + gid * FP + ks * 8 + tg];
            pf[1] = Ps[pbase + (gid + 8) * FP + ks * 8 + tg];
            pf[2] = Ps[pbase + gid * FP + ks * 8 + tg + 4];
            pf[3] = Ps[pbase + (gid + 8) * FP + ks * 8 + tg + 4];
#pragma unroll
            for (int n_ = 0; n_ < 8; n_++) {
                uint32_t b0 = Vt[(n_ * 8 + gid) * FP + ks * 8 + tg];
                uint32_t b1 = Vt[(n_ * 8 + gid) * FP + ks * 8 + tg + 4];
                mma_1688(o[n_], pf, b0, b1);
            }
        }
        __syncwarp();
    }

    // ---- epilogue: normalize, store ----
    const float inv0 = 1.0f / l0r, inv1 = 1.0f / l1r;
    float* Og = g_attn + (size_t)(b * SS + q0 + wq) * CC + h * DD;
#pragma unroll
    for (int n_ = 0; n_ < 8; n_++) {
        int col = n_ * 8 + tg * 2;
        float2 lo = make_float2(o[n_][0] * inv0, o[n_][1] * inv0);
        float2 hi = make_float2(o[n_][2] * inv1, o[n_][3] * inv1);
        *(float2*)(Og + (size_t)gid * CC + col)       = lo;
        *(float2*)(Og + (size_t)(gid + 8) * CC + col) = hi;
    }
}

// ---------------------------------------------------------------------------
extern "C" void kernel_launch(void* const* d_in, const int* in_sizes, int n_in,
                              void* d_out, int out_size)
{
    (void)in_sizes; (void)n_in; (void)out_size;
    const float* X  = (const float*)d_in[0];
    const float* Wq = (const float*)d_in[1];
    const float* Wk = (const float*)d_in[2];
    const float* Wv = (const float*)d_in[3];
    const float* Wo = (const float*)d_in[4];
    const float* bo = (const float*)d_in[5];
    float* out = (float*)d_out;

    cudaFuncSetAttribute(k_attn_mma, cudaFuncAttributeMaxDynamicSharedMemorySize,
                         ATT_SMEM);

    k_qkv_mma<<<dim3(CC / 128, (BB * SS) / 128, 3), 256>>>(X, Wq, Wk, Wv);
    k_transv<<<dim3(SS / 32, DD / 32, BB * HH), dim3(32, 8)>>>();
    k_stats<<<dim3(CC / 128, BB, 2), 128>>>();
    k_finalize<<<(2 * BB * CC + 255) / 256, 256>>>();
    k_apply<<<(2 * BB * SS * CC / 4 + 255) / 256, 256>>>();
    k_attn_mma<<<dim3(SS / 128, BB * HH), 256, ATT_SMEM>>>();
    k_proj_mma<<<dim3(CC / 128, (BB * SS) / 128), 256>>>(Wo, bo, out);
}

// round 7
// speedup vs baseline: 2.8777x; 1.0898x over previous
#include <cuda_runtime.h>
#include <cstdint>
#include <math.h>

// Problem constants
#define BB 4
#define SS 1024
#define CC 1280
#define HH 20
#define DD 64
#define ATT_SCALE 0.125f              // 64^-0.5
#define SHIFTV 0.6931471805599453f    // log(2)
#define EPSV 1e-5f

// ---------------- scratch (static device allocations are allowed) -----------
#define XN (BB*SS*CC)     // 5242880
#define WN (CC*CC)        // 1638400
__device__ float g_tf[XN + 4*WN];     // tf32-rounded [X | Wq | Wk | Wv | Wo]
__device__ float g_q[BB*SS*CC];
__device__ float g_k[BB*SS*CC];
__device__ float g_v[BB*SS*CC];
__device__ float g_vt[BB*SS*CC];      // V transposed (tf32-rounded): [b][h][d][s]
__device__ float g_attn[BB*SS*CC];    // tf32-rounded attention output
__device__ float g_mean[2*BB*CC];
__device__ float g_std[2*BB*CC];
__device__ float g_scl[2*BB*CC];
__device__ float g_shf[2*BB*CC];

// =================== helpers (sm_80+ PTX, base-target safe) ================
__device__ __forceinline__ uint32_t f2tf32(float x) {
    uint32_t r;
    asm("cvt.rna.tf32.f32 %0, %1;" : "=r"(r) : "f"(x));
    return r;
}

__device__ __forceinline__ void mma_1688(
    float c[4], const uint32_t a[4], uint32_t b0, uint32_t b1)
{
    asm volatile(
        "mma.sync.aligned.m16n8k8.row.col.f32.tf32.tf32.f32 "
        "{%0,%1,%2,%3}, {%4,%5,%6,%7}, {%8,%9}, {%0,%1,%2,%3};\n"
        : "+f"(c[0]), "+f"(c[1]), "+f"(c[2]), "+f"(c[3])
        : "r"(a[0]), "r"(a[1]), "r"(a[2]), "r"(a[3]), "r"(b0), "r"(b1));
}

__device__ __forceinline__ uint32_t smem_u32(const void* p) {
    uint32_t a;
    asm("{ .reg .u64 t; cvta.to.shared.u64 t, %1; cvt.u32.u64 %0, t; }"
        : "=r"(a) : "l"(p));
    return a;
}

#define CP_ASYNC16(dst, src) \
    asm volatile("cp.async.cg.shared.global [%0], [%1], 16;" \
        :: "r"(dst), "l"(src))
#define CP_COMMIT() asm volatile("cp.async.commit_group;")
#define CP_WAIT0()  asm volatile("cp.async.wait_group 0;")

// ---------------------------------------------------------------------------
// tf32 pre-rounding pass over [X | Wq | Wk | Wv | Wo]
// ---------------------------------------------------------------------------
#define CVT_F4 ((XN + 4*WN) / 4)     // 2949120 float4s
__global__ __launch_bounds__(256) void k_cvt(
    const float* __restrict__ X,  const float* __restrict__ Wq,
    const float* __restrict__ Wk, const float* __restrict__ Wv,
    const float* __restrict__ Wo)
{
    int i4 = blockIdx.x * 256 + threadIdx.x;
    if (i4 >= CVT_F4) return;
    const float* src;
    int base;
    if      (i4 < XN/4)          { src = X;  base = 0; }
    else if (i4 < (XN+WN)/4)     { src = Wq; base = XN/4; }
    else if (i4 < (XN+2*WN)/4)   { src = Wk; base = (XN+WN)/4; }
    else if (i4 < (XN+3*WN)/4)   { src = Wv; base = (XN+2*WN)/4; }
    else                         { src = Wo; base = (XN+3*WN)/4; }
    float4 v = ((const float4*)src)[i4 - base];
    uint4 t = make_uint4(f2tf32(v.x), f2tf32(v.y), f2tf32(v.z), f2tf32(v.w));
    ((uint4*)g_tf)[i4] = t;
}

// ---------------------------------------------------------------------------
// Tensor-core tf32 GEMM: C[m][n] = sum_k A[m][k] * W[n][k] (+bias[n])
// A and W must be pre-rounded to tf32. cp.async double-buffered, BK=16.
// Block 128x128, 256 threads / 8 warps (4m x 2n), warp tile 32x64.
// ---------------------------------------------------------------------------
#define BKP 20
#define GKT (CC / 16)   // 80 k-tiles

__device__ __forceinline__ void gemm_mma_body(
    const float* __restrict__ A, const float* __restrict__ W,
    const float* __restrict__ bias, float* __restrict__ Cout)
{
    __shared__ uint32_t As[2][128 * BKP];
    __shared__ uint32_t Bs[2][128 * BKP];

    const int tid  = threadIdx.x;
    const int warp = tid >> 5, lane = tid & 31;
    const int wm   = (warp & 3) * 32;
    const int wn   = (warp >> 2) * 64;
    const int tg   = lane & 3, gid = lane >> 2;
    const int m0   = blockIdx.y * 128;
    const int n0   = blockIdx.x * 128;

    const int lrow = tid >> 1;
    const int lc   = (tid & 1) * 8;
    const float* Ap = A + (size_t)(m0 + lrow) * CC + lc;
    const float* Bp = W + (size_t)(n0 + lrow) * CC + lc;

    const uint32_t sa0 = smem_u32(&As[0][lrow * BKP + lc]);
    const uint32_t sb0 = smem_u32(&Bs[0][lrow * BKP + lc]);
    const uint32_t sa1 = smem_u32(&As[1][lrow * BKP + lc]);
    const uint32_t sb1 = smem_u32(&Bs[1][lrow * BKP + lc]);

    float acc[2][8][4];
#pragma unroll
    for (int im = 0; im < 2; im++)
#pragma unroll
        for (int in_ = 0; in_ < 8; in_++)
#pragma unroll
            for (int r = 0; r < 4; r++) acc[im][in_][r] = 0.f;

    // prologue: kick tile 0 into buffer 0
    CP_ASYNC16(sa0,      Ap);
    CP_ASYNC16(sa0 + 16, Ap + 4);
    CP_ASYNC16(sb0,      Bp);
    CP_ASYNC16(sb0 + 16, Bp + 4);
    CP_COMMIT();

    for (int kt = 0; kt < GKT; kt++) {
        const int b = kt & 1;
        CP_WAIT0();
        __syncthreads();

        if (kt + 1 < GKT) {
            const float* An = Ap + (kt + 1) * 16;
            const float* Bn = Bp + (kt + 1) * 16;
            uint32_t da = b ? sa0 : sa1;
            uint32_t db = b ? sb0 : sb1;
            CP_ASYNC16(da,      An);
            CP_ASYNC16(da + 16, An + 4);
            CP_ASYNC16(db,      Bn);
            CP_ASYNC16(db + 16, Bn + 4);
            CP_COMMIT();
        }

        const uint32_t* sa = As[b];
        const uint32_t* sb = Bs[b];
#pragma unroll
        for (int ks = 0; ks < 16; ks += 8) {
            uint32_t af[2][4];
#pragma unroll
            for (int im = 0; im < 2; im++) {
                int r = wm + im * 16 + gid;
                af[im][0] = sa[(r + 0) * BKP + ks + tg];
                af[im][1] = sa[(r + 8) * BKP + ks + tg];
                af[im][2] = sa[(r + 0) * BKP + ks + tg + 4];
                af[im][3] = sa[(r + 8) * BKP + ks + tg + 4];
            }
#pragma unroll
            for (int in_ = 0; in_ < 8; in_++) {
                int n = wn + in_ * 8 + gid;
                uint32_t b0 = sb[n * BKP + ks + tg];
                uint32_t b1 = sb[n * BKP + ks + tg + 4];
                mma_1688(acc[0][in_], af[0], b0, b1);
                mma_1688(acc[1][in_], af[1], b0, b1);
            }
        }
        __syncthreads();
    }

#pragma unroll
    for (int im = 0; im < 2; im++) {
        int row = m0 + wm + im * 16 + gid;
#pragma unroll
        for (int in_ = 0; in_ < 8; in_++) {
            int col = n0 + wn + in_ * 8 + tg * 2;
            float b0v = 0.f, b1v = 0.f;
            if (bias) { b0v = bias[col]; b1v = bias[col + 1]; }
            float2 lo = make_float2(acc[im][in_][0] + b0v, acc[im][in_][1] + b1v);
            float2 hi = make_float2(acc[im][in_][2] + b0v, acc[im][in_][3] + b1v);
            *(float2*)(Cout + (size_t)row * CC + col)       = lo;
            *(float2*)(Cout + (size_t)(row + 8) * CC + col) = hi;
        }
    }
}

__global__ __launch_bounds__(256) void k_qkv_mma()
{
    const float* X = g_tf;
    const float* W = g_tf + XN + (size_t)blockIdx.z * WN;
    float* O;
    if (blockIdx.z == 0)      O = g_q;
    else if (blockIdx.z == 1) O = g_k;
    else                      O = g_v;
    gemm_mma_body(X, W, nullptr, O);
}

__global__ __launch_bounds__(256) void k_proj_mma(
    const float* __restrict__ bo, float* __restrict__ out)
{
    gemm_mma_body(g_attn, g_tf + XN + 3 * (size_t)WN, bo, out);
}

// ---------------------------------------------------------------------------
// V transpose + tf32 round: g_v [b][s][h][d] -> g_vt [b][h][d][s]
// ---------------------------------------------------------------------------
__global__ __launch_bounds__(256) void k_transv()
{
    __shared__ float tile[32][33];
    const int bh = blockIdx.z;
    const int b  = bh / HH, h = bh % HH;
    const int s0 = blockIdx.x * 32;
    const int d0 = blockIdx.y * 32;
    const int tx = threadIdx.x, ty = threadIdx.y;

    const float* src = g_v + (size_t)(b * SS + s0) * CC + h * DD + d0;
#pragma unroll
    for (int j = 0; j < 32; j += 8)
        tile[ty + j][tx] = src[(size_t)(ty + j) * CC + tx];
    __syncthreads();

    float* dst = g_vt + ((size_t)(b * HH + h) * DD + d0) * SS + s0;
#pragma unroll
    for (int j = 0; j < 32; j += 8)
        dst[(size_t)(ty + j) * SS + tx] = __uint_as_float(f2tf32(tile[tx][ty + j]));
}

// ---------------------------------------------------------------------------
// AdaIN stats / finalize / apply (apply emits tf32-rounded values)
// ---------------------------------------------------------------------------
__global__ void k_stats()
{
    const int c = blockIdx.x * 128 + threadIdx.x;
    const int b = blockIdx.y;
    const int z = blockIdx.z;
    const float* src = z ? g_k : g_q;
    const float* p = src + (size_t)b * SS * CC + c;

    float s0 = 0, s1 = 0, s2 = 0, s3 = 0;
    float q0 = 0, q1 = 0, q2 = 0, q3 = 0;
    for (int s = 0; s < SS; s += 4) {
        float x0 = p[(size_t)(s + 0) * CC];
        float x1 = p[(size_t)(s + 1) * CC];
        float x2 = p[(size_t)(s + 2) * CC];
        float x3 = p[(size_t)(s + 3) * CC];
        s0 += x0; q0 = fmaf(x0, x0, q0);
        s1 += x1; q1 = fmaf(x1, x1, q1);
        s2 += x2; q2 = fmaf(x2, x2, q2);
        s3 += x3; q3 = fmaf(x3, x3, q3);
    }
    float sum = (s0 + s1) + (s2 + s3);
    float sq  = (q0 + q1) + (q2 + q3);
    float mean = sum * (1.0f / SS);
    float var  = (sq - sum * mean) * (1.0f / (SS - 1));
    float sd   = sqrtf(var + EPSV);
    g_mean[(z * BB + b) * CC + c] = mean;
    g_std [(z * BB + b) * CC + c] = sd;
}

__global__ void k_finalize()
{
    int i = blockIdx.x * 256 + threadIdx.x;
    if (i >= 2 * BB * CC) return;
    int c  = i % CC;
    int b  = (i / CC) % BB;
    int z  = i / (CC * BB);
    int sb = (b < BB / 2) ? 0 : BB / 2;
    float sd  = g_std [(z * BB + b)  * CC + c];
    float sds = g_std [(z * BB + sb) * CC + c];
    float mn  = g_mean[(z * BB + b)  * CC + c];
    float mns = g_mean[(z * BB + sb) * CC + c];
    float scl = sds / sd;
    g_scl[i] = scl;
    g_shf[i] = mns - mn * scl;
}

__global__ void k_apply()
{
    const int TOT4  = 2 * BB * SS * CC / 4;
    const int per_t = SS * CC / 4;
    int i4 = blockIdx.x * 256 + threadIdx.x;
    if (i4 >= TOT4) return;
    int zb = i4 / per_t;
    int r  = i4 % per_t;
    int c  = (r % (CC / 4)) * 4;
    float* buf = (zb < BB) ? g_q : g_k;
    int b = zb & 3;
    float4* p = (float4*)buf + (size_t)b * per_t + r;
    float4 scl = *(const float4*)&g_scl[zb * CC + c];
    float4 shf = *(const float4*)&g_shf[zb * CC + c];
    float4 x = *p;
    uint4 t;
    t.x = f2tf32(fmaf(x.x, scl.x, shf.x));
    t.y = f2tf32(fmaf(x.y, scl.y, shf.y));
    t.z = f2tf32(fmaf(x.z, scl.z, shf.z));
    t.w = f2tf32(fmaf(x.w, scl.w, shf.w));
    *(uint4*)p = t;
}

// ---------------------------------------------------------------------------
// Flash attention on tensor cores (tf32 mma.sync), cp.async double-buffered
// K/V. CTA: 128 queries of one (b,h). 8 warps x 16 q-rows. Chunks of 64 keys,
// 32 chunks (16 self + 16 style, style gets +log2 bias). All inputs are
// pre-rounded to tf32 so cp.async raw copies are exact.
// ---------------------------------------------------------------------------
#define FP 68                       // smem pitch (words), 68 % 32 == 4
#define KS_OFF(b) ((b) * 128 * FP)
#define VS_OFF(b) ((b) * 128 * FP + 64 * FP)
#define PS_OFF    (256 * FP)
#define ATT_SMEM  (384 * FP * 4)    // 104448 bytes

__global__ __launch_bounds__(256, 2) void k_attn_mma()
{
    extern __shared__ uint32_t sm[];
    uint32_t* Ps = sm + PS_OFF;

    const int tid  = threadIdx.x;
    const int warp = tid >> 5, lane = tid & 31;
    const int tg   = lane & 3, gid = lane >> 2;
    const int bh   = blockIdx.y;
    const int b    = bh / HH;
    const int h    = bh % HH;
    const int q0   = blockIdx.x * 128;
    const int sbv  = (b < BB / 2) ? 0 : BB / 2;
    const int wq   = warp * 16;

    const uint32_t smb = smem_u32(sm);
    const int frow = tid >> 4, fc4 = tid & 15;   // fill pattern base

    // ---- stage Q tile (128 x 64, already tf32) into Ps, grab frags ----
    {
        const float* Qg = g_q + (size_t)(b * SS + q0) * CC + h * DD;
#pragma unroll
        for (int i = 0; i < 8; i++) {
            int fid = tid + i * 256;
            int row = fid >> 4, c4 = fid & 15;
            *(uint4*)(Ps + row * FP + c4 * 4) =
                *(const uint4*)(Qg + (size_t)row * CC + c4 * 4);
        }
    }
    __syncthreads();

    uint32_t qf[8][4];
#pragma unroll
    for (int ks = 0; ks < 8; ks++) {
        qf[ks][0] = Ps[(wq + gid) * FP + ks * 8 + tg];
        qf[ks][1] = Ps[(wq + gid + 8) * FP + ks * 8 + tg];
        qf[ks][2] = Ps[(wq + gid) * FP + ks * 8 + tg + 4];
        qf[ks][3] = Ps[(wq + gid + 8) * FP + ks * 8 + tg + 4];
    }
    __syncthreads();   // Q staging reads done; Ps now free for P tiles

    float o[8][4];
#pragma unroll
    for (int n_ = 0; n_ < 8; n_++)
#pragma unroll
        for (int r = 0; r < 4; r++) o[n_][r] = 0.f;
    float m0r = -1e30f, m1r = -1e30f, l0r = 0.f, l1r = 0.f;

    // chunk source helper data
    const float* Kbase0 = g_k + (size_t)b * SS * CC + h * DD;
    const float* Kbase1 = g_k + (size_t)sbv * SS * CC + h * DD;
    const float* Vbase0 = g_vt + ((size_t)(b * HH + h) * DD) * SS;
    const float* Vbase1 = g_vt + ((size_t)(sbv * HH + h) * DD) * SS;

    // prologue: kick chunk 0 into buffer 0
    {
        const float* Kg = Kbase0;
        const float* Vg = Vbase0;
        uint32_t kd = smb + (KS_OFF(0) + frow * FP + fc4 * 4) * 4;
        uint32_t vd = smb + (VS_OFF(0) + frow * FP + fc4 * 4) * 4;
#pragma unroll
        for (int i = 0; i < 4; i++) {
            int row = frow + i * 16;
            CP_ASYNC16(kd + i * 16 * FP * 4, Kg + (size_t)row * CC + fc4 * 4);
            CP_ASYNC16(vd + i * 16 * FP * 4, Vg + (size_t)row * SS + fc4 * 4);
        }
        CP_COMMIT();
    }

    for (int ch = 0; ch < 32; ch++) {
        const int  bb   = ch & 1;
        const float bias = (ch < 16) ? 0.f : SHIFTV;

        CP_WAIT0();
        __syncthreads();   // chunk ch visible to all; prev reads of buf bb done

        if (ch + 1 < 32) {
            const int self2 = (ch + 1 < 16);
            const int kr2   = (self2 ? ch + 1 : ch - 15) * 64;
            const float* Kg = (self2 ? Kbase0 : Kbase1) + (size_t)kr2 * CC;
            const float* Vg = (self2 ? Vbase0 : Vbase1) + kr2;
            uint32_t kd = smb + (KS_OFF(bb ^ 1) + frow * FP + fc4 * 4) * 4;
            uint32_t vd = smb + (VS_OFF(bb ^ 1) + frow * FP + fc4 * 4) * 4;
#pragma unroll
            for (int i = 0; i < 4; i++) {
                int row = frow + i * 16;
                CP_ASYNC16(kd + i * 16 * FP * 4, Kg + (size_t)row * CC + fc4 * 4);
                CP_ASYNC16(vd + i * 16 * FP * 4, Vg + (size_t)row * SS + fc4 * 4);
            }
            CP_COMMIT();
        }

        const uint32_t* Ks = sm + KS_OFF(bb);
        const uint32_t* Vt = sm + VS_OFF(bb);

        // ---- S = Q @ K^T  (16 x 64 per warp) ----
        float sacc[8][4];
#pragma unroll
        for (int n_ = 0; n_ < 8; n_++)
#pragma unroll
            for (int r = 0; r < 4; r++) sacc[n_][r] = 0.f;

#pragma unroll
        for (int ks = 0; ks < 8; ks++) {
#pragma unroll
            for (int n_ = 0; n_ < 8; n_++) {
                uint32_t b0 = Ks[(n_ * 8 + gid) * FP + ks * 8 + tg];
                uint32_t b1 = Ks[(n_ * 8 + gid) * FP + ks * 8 + tg + 4];
                mma_1688(sacc[n_], qf[ks], b0, b1);
            }
        }

        // ---- online softmax (rows gid -> c0/c1, gid+8 -> c2/c3) ----
        float mx0 = -1e30f, mx1 = -1e30f;
#pragma unroll
        for (int n_ = 0; n_ < 8; n_++) {
            sacc[n_][0] = fmaf(sacc[n_][0], ATT_SCALE, bias);
            sacc[n_][1] = fmaf(sacc[n_][1], ATT_SCALE, bias);
            sacc[n_][2] = fmaf(sacc[n_][2], ATT_SCALE, bias);
            sacc[n_][3] = fmaf(sacc[n_][3], ATT_SCALE, bias);
            mx0 = fmaxf(mx0, fmaxf(sacc[n_][0], sacc[n_][1]));
            mx1 = fmaxf(mx1, fmaxf(sacc[n_][2], sacc[n_][3]));
        }
        mx0 = fmaxf(mx0, __shfl_xor_sync(0xffffffffu, mx0, 1));
        mx0 = fmaxf(mx0, __shfl_xor_sync(0xffffffffu, mx0, 2));
        mx1 = fmaxf(mx1, __shfl_xor_sync(0xffffffffu, mx1, 1));
        mx1 = fmaxf(mx1, __shfl_xor_sync(0xffffffffu, mx1, 2));

        float mn0 = fmaxf(m0r, mx0), mn1 = fmaxf(m1r, mx1);
        float al0 = __expf(m0r - mn0), al1 = __expf(m1r - mn1);
        m0r = mn0; m1r = mn1;

        float rs0 = 0.f, rs1 = 0.f;
        const uint32_t pbase = wq * FP;
#pragma unroll
        for (int n_ = 0; n_ < 8; n_++) {
            float p0 = __expf(sacc[n_][0] - mn0);
            float p1 = __expf(sacc[n_][1] - mn0);
            float p2 = __expf(sacc[n_][2] - mn1);
            float p3 = __expf(sacc[n_][3] - mn1);
            rs0 += p0 + p1; rs1 += p2 + p3;
            uint2 lo = make_uint2(f2tf32(p0), f2tf32(p1));
            uint2 hi = make_uint2(f2tf32(p2), f2tf32(p3));
            *(uint2*)(Ps + pbase + gid * FP + n_ * 8 + tg * 2)       = lo;
            *(uint2*)(Ps + pbase + (gid + 8) * FP + n_ * 8 + tg * 2) = hi;
        }
        rs0 += __shfl_xor_sync(0xffffffffu, rs0, 1);
        rs0 += __shfl_xor_sync(0xffffffffu, rs0, 2);
        rs1 += __shfl_xor_sync(0xffffffffu, rs1, 1);
        rs1 += __shfl_xor_sync(0xffffffffu, rs1, 2);
        l0r = l0r * al0 + rs0;
        l1r = l1r * al1 + rs1;

#pragma unroll
        for (int n_ = 0; n_ < 8; n_++) {
            o[n_][0] *= al0; o[n_][1] *= al0;
            o[n_][2] *= al1; o[n_][3] *= al1;
        }
        __syncwarp();

        // ---- O += P @ V  (A = warp-private P, B = Vt) ----
#pragma unroll
        for (int ks = 0; ks < 8; ks++) {
            uint32_t pf[4];
            pf[0] = Ps[pbase + gid * FP + ks * 8 + tg];
            pf[1] = Ps[pbase + (gid + 8) * FP + ks * 8 + tg];
            pf[2] = Ps[pbase + gid * FP + ks * 8 + tg + 4];
            pf[3] = Ps[pbase + (gid + 8) * FP + ks * 8 + tg + 4];
#pragma unroll
            for (int n_ = 0; n_ < 8; n_++) {
                uint32_t b0 = Vt[(n_ * 8 + gid) * FP + ks * 8 + tg];
                uint32_t b1 = Vt[(n_ * 8 + gid) * FP + ks * 8 + tg + 4];
                mma_1688(o[n_], pf, b0, b1);
            }
        }
        __syncthreads();   // reads of buf bb done before it is refilled
    }

    // ---- epilogue: normalize, tf32-round, store ----
    const float inv0 = 1.0f / l0r, inv1 = 1.0f / l1r;
    float* Og = g_attn + (size_t)(b * SS + q0 + wq) * CC + h * DD;
#pragma unroll
    for (int n_ = 0; n_ < 8; n_++) {
        int col = n_ * 8 + tg * 2;
        uint2 lo = make_uint2(f2tf32(o[n_][0] * inv0), f2tf32(o[n_][1] * inv0));
        uint2 hi = make_uint2(f2tf32(o[n_][2] * inv1), f2tf32(o[n_][3] * inv1));
        *(uint2*)(Og + (size_t)gid * CC + col)       = lo;
        *(uint2*)(Og + (size_t)(gid + 8) * CC + col) = hi;
    }
}

// ---------------------------------------------------------------------------
extern "C" void kernel_launch(void* const* d_in, const int* in_sizes, int n_in,
                              void* d_out, int out_size)
{
    (void)in_sizes; (void)n_in; (void)out_size;
    const float* X  = (const float*)d_in[0];
    const float* Wq = (const float*)d_in[1];
    const float* Wk = (const float*)d_in[2];
    const float* Wv = (const float*)d_in[3];
    const float* Wo = (const float*)d_in[4];
    const float* bo = (const float*)d_in[5];
    float* out = (float*)d_out;

    cudaFuncSetAttribute(k_attn_mma, cudaFuncAttributeMaxDynamicSharedMemorySize,
                         ATT_SMEM);

    k_cvt<<<(CVT_F4 + 255) / 256, 256>>>(X, Wq, Wk, Wv, Wo);
    k_qkv_mma<<<dim3(CC / 128, (BB * SS) / 128, 3), 256>>>();
    k_transv<<<dim3(SS / 32, DD / 32, BB * HH), dim3(32, 8)>>>();
    k_stats<<<dim3(CC / 128, BB, 2), 128>>>();
    k_finalize<<<(2 * BB * CC + 255) / 256, 256>>>();
    k_apply<<<(2 * BB * SS * CC / 4 + 255) / 256, 256>>>();
    k_attn_mma<<<dim3(SS / 128, BB * HH), 256, ATT_SMEM>>>();
    k_proj_mma<<<dim3(CC / 128, (BB * SS) / 128), 256>>>(bo, out);
}

// round 8
// speedup vs baseline: 3.4042x; 1.1829x over previous
#include <cuda_runtime.h>
#include <cstdint>
#include <math.h>

// Problem constants
#define BB 4
#define SS 1024
#define CC 1280
#define HH 20
#define DD 64
#define ATT_SCALE 0.125f              // 64^-0.5
#define SHIFTV 0.6931471805599453f    // log(2)
#define EPSV 1e-5f

// ---------------- scratch (static device allocations are allowed) -----------
#define XN (BB*SS*CC)     // 5242880
#define WN (CC*CC)        // 1638400
__device__ float g_tf[XN + 4*WN];     // tf32-rounded [X | Wq | Wk | Wv | Wo]
__device__ float g_q[BB*SS*CC];
__device__ float g_k[BB*SS*CC];
__device__ float g_v[BB*SS*CC];
__device__ float g_vt[BB*SS*CC];      // V transposed (tf32-rounded): [b][h][d][s]
__device__ float g_attn[BB*SS*CC];    // tf32-rounded attention output
__device__ float g_psum[2*BB*8*CC];   // stats partials: [z][b][seg][c]
__device__ float g_psq [2*BB*8*CC];
__device__ float g_scl[2*BB*CC];
__device__ float g_shf[2*BB*CC];

// =================== helpers (sm_75+/sm_80+ PTX, base-target safe) =========
__device__ __forceinline__ uint32_t f2tf32(float x) {
    uint32_t r;
    asm("cvt.rna.tf32.f32 %0, %1;" : "=r"(r) : "f"(x));
    return r;
}

__device__ __forceinline__ void mma_1688(
    float c[4], const uint32_t a[4], uint32_t b0, uint32_t b1)
{
    asm volatile(
        "mma.sync.aligned.m16n8k8.row.col.f32.tf32.tf32.f32 "
        "{%0,%1,%2,%3}, {%4,%5,%6,%7}, {%8,%9}, {%0,%1,%2,%3};\n"
        : "+f"(c[0]), "+f"(c[1]), "+f"(c[2]), "+f"(c[3])
        : "r"(a[0]), "r"(a[1]), "r"(a[2]), "r"(a[3]), "r"(b0), "r"(b1));
}

__device__ __forceinline__ uint32_t smem_u32(const void* p) {
    uint32_t a;
    asm("{ .reg .u64 t; cvta.to.shared.u64 t, %1; cvt.u32.u64 %0, t; }"
        : "=r"(a) : "l"(p));
    return a;
}

#define LDSM_X4(R, addr) \
    asm volatile("ldmatrix.sync.aligned.m8n8.x4.shared.b16 {%0,%1,%2,%3}, [%4];" \
        : "=r"((R)[0]), "=r"((R)[1]), "=r"((R)[2]), "=r"((R)[3]) : "r"(addr))

#define CP_ASYNC16(dst, src) \
    asm volatile("cp.async.cg.shared.global [%0], [%1], 16;" \
        :: "r"(dst), "l"(src))
#define CP_COMMIT() asm volatile("cp.async.commit_group;")
#define CP_WAIT0()  asm volatile("cp.async.wait_group 0;")

// ---------------------------------------------------------------------------
// tf32 pre-rounding pass over [X | Wq | Wk | Wv | Wo]
// ---------------------------------------------------------------------------
#define CVT_F4 ((XN + 4*WN) / 4)
__global__ __launch_bounds__(256) void k_cvt(
    const float* __restrict__ X,  const float* __restrict__ Wq,
    const float* __restrict__ Wk, const float* __restrict__ Wv,
    const float* __restrict__ Wo)
{
    int i4 = blockIdx.x * 256 + threadIdx.x;
    if (i4 >= CVT_F4) return;
    const float* src;
    int base;
    if      (i4 < XN/4)          { src = X;  base = 0; }
    else if (i4 < (XN+WN)/4)     { src = Wq; base = XN/4; }
    else if (i4 < (XN+2*WN)/4)   { src = Wk; base = (XN+WN)/4; }
    else if (i4 < (XN+3*WN)/4)   { src = Wv; base = (XN+2*WN)/4; }
    else                         { src = Wo; base = (XN+3*WN)/4; }
    float4 v = ((const float4*)src)[i4 - base];
    uint4 t = make_uint4(f2tf32(v.x), f2tf32(v.y), f2tf32(v.z), f2tf32(v.w));
    ((uint4*)g_tf)[i4] = t;
}

// ---------------------------------------------------------------------------
// Tensor-core tf32 GEMM with LDSM fragment loads.
// Block 128x128, BK=16, 256 threads / 8 warps (4m x 2n), warp tile 32x64.
// ---------------------------------------------------------------------------
#define BKP 20
#define GKT (CC / 16)   // 80 k-tiles

__device__ __forceinline__ void gemm_mma_body(
    const float* __restrict__ A, const float* __restrict__ W,
    const float* __restrict__ bias, float* __restrict__ Cout)
{
    __shared__ __align__(16) uint32_t As[2][128 * BKP];
    __shared__ __align__(16) uint32_t Bs[2][128 * BKP];

    const int tid  = threadIdx.x;
    const int warp = tid >> 5, lane = tid & 31;
    const int wm   = (warp & 3) * 32;
    const int wn   = (warp >> 2) * 64;
    const int tg   = lane & 3, gid = lane >> 2;
    const int m0   = blockIdx.y * 128;
    const int n0   = blockIdx.x * 128;

    const int lrow = tid >> 1;
    const int lc   = (tid & 1) * 8;
    const float* Ap = A + (size_t)(m0 + lrow) * CC + lc;
    const float* Bp = W + (size_t)(n0 + lrow) * CC + lc;

    const uint32_t sa0 = smem_u32(&As[0][lrow * BKP + lc]);
    const uint32_t sb0 = smem_u32(&Bs[0][lrow * BKP + lc]);
    const uint32_t sa1 = smem_u32(&As[1][lrow * BKP + lc]);
    const uint32_t sb1 = smem_u32(&Bs[1][lrow * BKP + lc]);

    // LDSM lane address offsets (bytes)
    const int lr   = lane & 7;
    const int lhi8 = (lane >> 3) & 1;         // +8 rows (A map)
    const int lcg4 = (lane >> 4) & 1;         // +4 cols (A map)
    const uint32_t aoff = ((wm + lhi8 * 8 + lr) * BKP + lcg4 * 4) * 4;
    const uint32_t boff = ((wn + (lane >> 4) * 8 + lr) * BKP + ((lane >> 3) & 1) * 4) * 4;
    const uint32_t aB[2] = { smem_u32(As[0]) + aoff, smem_u32(As[1]) + aoff };
    const uint32_t bB[2] = { smem_u32(Bs[0]) + boff, smem_u32(Bs[1]) + boff };

    float acc[2][8][4];
#pragma unroll
    for (int im = 0; im < 2; im++)
#pragma unroll
        for (int in_ = 0; in_ < 8; in_++)
#pragma unroll
            for (int r = 0; r < 4; r++) acc[im][in_][r] = 0.f;

    CP_ASYNC16(sa0,      Ap);
    CP_ASYNC16(sa0 + 16, Ap + 4);
    CP_ASYNC16(sb0,      Bp);
    CP_ASYNC16(sb0 + 16, Bp + 4);
    CP_COMMIT();

    for (int kt = 0; kt < GKT; kt++) {
        const int b = kt & 1;
        CP_WAIT0();
        __syncthreads();

        if (kt + 1 < GKT) {
            const float* An = Ap + (kt + 1) * 16;
            const float* Bn = Bp + (kt + 1) * 16;
            uint32_t da = b ? sa0 : sa1;
            uint32_t db = b ? sb0 : sb1;
            CP_ASYNC16(da,      An);
            CP_ASYNC16(da + 16, An + 4);
            CP_ASYNC16(db,      Bn);
            CP_ASYNC16(db + 16, Bn + 4);
            CP_COMMIT();
        }

        const uint32_t sal = aB[b];
        const uint32_t sbl = bB[b];
#pragma unroll
        for (int ks = 0; ks < 16; ks += 8) {
            uint32_t af[2][4];
            LDSM_X4(af[0], sal + ks * 4);
            LDSM_X4(af[1], sal + 16 * BKP * 4 + ks * 4);
#pragma unroll
            for (int np = 0; np < 4; np++) {
                uint32_t bf[4];
                LDSM_X4(bf, sbl + np * 16 * BKP * 4 + ks * 4);
                mma_1688(acc[0][2*np],     af[0], bf[0], bf[1]);
                mma_1688(acc[0][2*np + 1], af[0], bf[2], bf[3]);
                mma_1688(acc[1][2*np],     af[1], bf[0], bf[1]);
                mma_1688(acc[1][2*np + 1], af[1], bf[2], bf[3]);
            }
        }
        __syncthreads();
    }

#pragma unroll
    for (int im = 0; im < 2; im++) {
        int row = m0 + wm + im * 16 + gid;
#pragma unroll
        for (int in_ = 0; in_ < 8; in_++) {
            int col = n0 + wn + in_ * 8 + tg * 2;
            float b0v = 0.f, b1v = 0.f;
            if (bias) { b0v = bias[col]; b1v = bias[col + 1]; }
            float2 lo = make_float2(acc[im][in_][0] + b0v, acc[im][in_][1] + b1v);
            float2 hi = make_float2(acc[im][in_][2] + b0v, acc[im][in_][3] + b1v);
            *(float2*)(Cout + (size_t)row * CC + col)       = lo;
            *(float2*)(Cout + (size_t)(row + 8) * CC + col) = hi;
        }
    }
}

__global__ __launch_bounds__(256) void k_qkv_mma()
{
    const float* X = g_tf;
    const float* W = g_tf + XN + (size_t)blockIdx.z * WN;
    float* O;
    if (blockIdx.z == 0)      O = g_q;
    else if (blockIdx.z == 1) O = g_k;
    else                      O = g_v;
    gemm_mma_body(X, W, nullptr, O);
}

__global__ __launch_bounds__(256) void k_proj_mma(
    const float* __restrict__ bo, float* __restrict__ out)
{
    gemm_mma_body(g_attn, g_tf + XN + 3 * (size_t)WN, bo, out);
}

// ---------------------------------------------------------------------------
// V transpose + tf32 round: g_v [b][s][h][d] -> g_vt [b][h][d][s]
// ---------------------------------------------------------------------------
__global__ __launch_bounds__(256) void k_transv()
{
    __shared__ float tile[32][33];
    const int bh = blockIdx.z;
    const int b  = bh / HH, h = bh % HH;
    const int s0 = blockIdx.x * 32;
    const int d0 = blockIdx.y * 32;
    const int tx = threadIdx.x, ty = threadIdx.y;

    const float* src = g_v + (size_t)(b * SS + s0) * CC + h * DD + d0;
#pragma unroll
    for (int j = 0; j < 32; j += 8)
        tile[ty + j][tx] = src[(size_t)(ty + j) * CC + tx];
    __syncthreads();

    float* dst = g_vt + ((size_t)(b * HH + h) * DD + d0) * SS + s0;
#pragma unroll
    for (int j = 0; j < 32; j += 8)
        dst[(size_t)(ty + j) * SS + tx] = __uint_as_float(f2tf32(tile[tx][ty + j]));
}

// ---------------------------------------------------------------------------
// AdaIN stats: split-S partial sums (8 segments of 128 rows) for occupancy.
// ---------------------------------------------------------------------------
__global__ void k_stats()
{
    const int c   = blockIdx.x * 128 + threadIdx.x;
    const int b   = blockIdx.y;
    const int z   = blockIdx.z >> 3;
    const int seg = blockIdx.z & 7;
    const float* src = z ? g_k : g_q;
    const float* p = src + ((size_t)b * SS + seg * 128) * CC + c;

    float s0 = 0, s1 = 0, q0 = 0, q1 = 0;
#pragma unroll 4
    for (int s = 0; s < 128; s += 2) {
        float x0 = p[(size_t)(s + 0) * CC];
        float x1 = p[(size_t)(s + 1) * CC];
        s0 += x0; q0 = fmaf(x0, x0, q0);
        s1 += x1; q1 = fmaf(x1, x1, q1);
    }
    int idx = ((z * BB + b) * 8 + seg) * CC + c;
    g_psum[idx] = s0 + s1;
    g_psq [idx] = q0 + q1;
}

__global__ void k_finalize()
{
    int i = blockIdx.x * 256 + threadIdx.x;   // (z*BB+b)*CC + c
    if (i >= 2 * BB * CC) return;
    int c  = i % CC;
    int b  = (i / CC) % BB;
    int z  = i / (CC * BB);
    int sb = (b < BB / 2) ? 0 : BB / 2;

    float sum = 0, sq = 0, sums = 0, sqs = 0;
#pragma unroll
    for (int seg = 0; seg < 8; seg++) {
        sum  += g_psum[((z * BB + b)  * 8 + seg) * CC + c];
        sq   += g_psq [((z * BB + b)  * 8 + seg) * CC + c];
        sums += g_psum[((z * BB + sb) * 8 + seg) * CC + c];
        sqs  += g_psq [((z * BB + sb) * 8 + seg) * CC + c];
    }
    float mean  = sum  * (1.0f / SS);
    float means = sums * (1.0f / SS);
    float sd  = sqrtf((sq  - sum  * mean ) * (1.0f / (SS - 1)) + EPSV);
    float sds = sqrtf((sqs - sums * means) * (1.0f / (SS - 1)) + EPSV);
    float scl = sds / sd;
    g_scl[i] = scl;
    g_shf[i] = means - mean * scl;
}

__global__ void k_apply()
{
    const int TOT4  = 2 * BB * SS * CC / 4;
    const int per_t = SS * CC / 4;
    int i4 = blockIdx.x * 256 + threadIdx.x;
    if (i4 >= TOT4) return;
    int zb = i4 / per_t;
    int r  = i4 % per_t;
    int c  = (r % (CC / 4)) * 4;
    float* buf = (zb < BB) ? g_q : g_k;
    int b = zb & 3;
    float4* p = (float4*)buf + (size_t)b * per_t + r;
    float4 scl = *(const float4*)&g_scl[zb * CC + c];
    float4 shf = *(const float4*)&g_shf[zb * CC + c];
    float4 x = *p;
    uint4 t;
    t.x = f2tf32(fmaf(x.x, scl.x, shf.x));
    t.y = f2tf32(fmaf(x.y, scl.y, shf.y));
    t.z = f2tf32(fmaf(x.z, scl.z, shf.z));
    t.w = f2tf32(fmaf(x.w, scl.w, shf.w));
    *(uint4*)p = t;
}

// ---------------------------------------------------------------------------
// Flash attention on tensor cores, LDSM fragment loads, cp.async K/V.
// CTA: 128 queries of one (b,h). 8 warps x 16 q-rows. 32 chunks of 64 keys
// (16 self + 16 style with +log2 bias). All inputs pre-rounded tf32.
// ---------------------------------------------------------------------------
#define FP 68                       // smem pitch (words), 68 % 32 == 4
#define KS_OFF(b) ((b) * 128 * FP)
#define VS_OFF(b) ((b) * 128 * FP + 64 * FP)
#define PS_OFF    (256 * FP)
#define ATT_SMEM  (384 * FP * 4)    // 104448 bytes

__global__ __launch_bounds__(256, 2) void k_attn_mma()
{
    extern __shared__ uint32_t sm[];
    uint32_t* Ps = sm + PS_OFF;

    const int tid  = threadIdx.x;
    const int warp = tid >> 5, lane = tid & 31;
    const int tg   = lane & 3, gid = lane >> 2;
    const int bh   = blockIdx.y;
    const int b    = bh / HH;
    const int h    = bh % HH;
    const int q0   = blockIdx.x * 128;
    const int sbv  = (b < BB / 2) ? 0 : BB / 2;
    const int wq   = warp * 16;

    const uint32_t smb = smem_u32(sm);
    const int frow = tid >> 4, fc4 = tid & 15;   // fill pattern base

    // LDSM lane offsets (bytes)
    const int lr   = lane & 7;
    const uint32_t aoff = ((wq + ((lane >> 3) & 1) * 8 + lr) * FP
                           + ((lane >> 4) & 1) * 4) * 4;       // A-map on P/Q rows
    const uint32_t kvoff = (((lane >> 4) * 8 + lr) * FP
                           + ((lane >> 3) & 1) * 4) * 4;       // B-map on K/V rows

    // ---- stage Q tile (128 x 64, already tf32) into Ps, grab frags ----
    {
        const float* Qg = g_q + (size_t)(b * SS + q0) * CC + h * DD;
#pragma unroll
        for (int i = 0; i < 8; i++) {
            int fid = tid + i * 256;
            int row = fid >> 4, c4 = fid & 15;
            *(uint4*)(Ps + row * FP + c4 * 4) =
                *(const uint4*)(Qg + (size_t)row * CC + c4 * 4);
        }
    }
    __syncthreads();

    uint32_t qf[8][4];
    {
        const uint32_t qaddr = smb + PS_OFF * 4 + aoff;
#pragma unroll
        for (int ks = 0; ks < 8; ks++) LDSM_X4(qf[ks], qaddr + ks * 32);
    }
    __syncthreads();   // Q staging reads done; Ps now free for P tiles

    float o[8][4];
#pragma unroll
    for (int n_ = 0; n_ < 8; n_++)
#pragma unroll
        for (int r = 0; r < 4; r++) o[n_][r] = 0.f;
    float m0r = -1e30f, m1r = -1e30f, l0r = 0.f, l1r = 0.f;

    const float* Kbase0 = g_k + (size_t)b * SS * CC + h * DD;
    const float* Kbase1 = g_k + (size_t)sbv * SS * CC + h * DD;
    const float* Vbase0 = g_vt + ((size_t)(b * HH + h) * DD) * SS;
    const float* Vbase1 = g_vt + ((size_t)(sbv * HH + h) * DD) * SS;

    // prologue: chunk 0 -> buffer 0
    {
        uint32_t kd = smb + (KS_OFF(0) + frow * FP + fc4 * 4) * 4;
        uint32_t vd = smb + (VS_OFF(0) + frow * FP + fc4 * 4) * 4;
#pragma unroll
        for (int i = 0; i < 4; i++) {
            int row = frow + i * 16;
            CP_ASYNC16(kd + i * 16 * FP * 4, Kbase0 + (size_t)row * CC + fc4 * 4);
            CP_ASYNC16(vd + i * 16 * FP * 4, Vbase0 + (size_t)row * SS + fc4 * 4);
        }
        CP_COMMIT();
    }

    for (int ch = 0; ch < 32; ch++) {
        const int  bb   = ch & 1;
        const float bias = (ch < 16) ? 0.f : SHIFTV;

        CP_WAIT0();
        __syncthreads();

        if (ch + 1 < 32) {
            const int self2 = (ch + 1 < 16);
            const int kr2   = (self2 ? ch + 1 : ch - 15) * 64;
            const float* Kg = (self2 ? Kbase0 : Kbase1) + (size_t)kr2 * CC;
            const float* Vg = (self2 ? Vbase0 : Vbase1) + kr2;
            uint32_t kd = smb + (KS_OFF(bb ^ 1) + frow * FP + fc4 * 4) * 4;
            uint32_t vd = smb + (VS_OFF(bb ^ 1) + frow * FP + fc4 * 4) * 4;
#pragma unroll
            for (int i = 0; i < 4; i++) {
                int row = frow + i * 16;
                CP_ASYNC16(kd + i * 16 * FP * 4, Kg + (size_t)row * CC + fc4 * 4);
                CP_ASYNC16(vd + i * 16 * FP * 4, Vg + (size_t)row * SS + fc4 * 4);
            }
            CP_COMMIT();
        }

        const uint32_t kbase = smb + KS_OFF(bb) * 4 + kvoff;
        const uint32_t vbase = smb + VS_OFF(bb) * 4 + kvoff;

        // ---- S = Q @ K^T  (16 x 64 per warp) ----
        float sacc[8][4];
#pragma unroll
        for (int n_ = 0; n_ < 8; n_++)
#pragma unroll
            for (int r = 0; r < 4; r++) sacc[n_][r] = 0.f;

#pragma unroll
        for (int ks = 0; ks < 8; ks++) {
#pragma unroll
            for (int np = 0; np < 4; np++) {
                uint32_t bf[4];
                LDSM_X4(bf, kbase + np * 16 * FP * 4 + ks * 32);
                mma_1688(sacc[2*np],     qf[ks], bf[0], bf[1]);
                mma_1688(sacc[2*np + 1], qf[ks], bf[2], bf[3]);
            }
        }

        // ---- online softmax (rows gid -> c0/c1, gid+8 -> c2/c3) ----
        float mx0 = -1e30f, mx1 = -1e30f;
#pragma unroll
        for (int n_ = 0; n_ < 8; n_++) {
            sacc[n_][0] = fmaf(sacc[n_][0], ATT_SCALE, bias);
            sacc[n_][1] = fmaf(sacc[n_][1], ATT_SCALE, bias);
            sacc[n_][2] = fmaf(sacc[n_][2], ATT_SCALE, bias);
            sacc[n_][3] = fmaf(sacc[n_][3], ATT_SCALE, bias);
            mx0 = fmaxf(mx0, fmaxf(sacc[n_][0], sacc[n_][1]));
            mx1 = fmaxf(mx1, fmaxf(sacc[n_][2], sacc[n_][3]));
        }
        mx0 = fmaxf(mx0, __shfl_xor_sync(0xffffffffu, mx0, 1));
        mx0 = fmaxf(mx0, __shfl_xor_sync(0xffffffffu, mx0, 2));
        mx1 = fmaxf(mx1, __shfl_xor_sync(0xffffffffu, mx1, 1));
        mx1 = fmaxf(mx1, __shfl_xor_sync(0xffffffffu, mx1, 2));

        float mn0 = fmaxf(m0r, mx0), mn1 = fmaxf(m1r, mx1);
        float al0 = __expf(m0r - mn0), al1 = __expf(m1r - mn1);
        m0r = mn0; m1r = mn1;

        float rs0 = 0.f, rs1 = 0.f;
        const uint32_t pbase = wq * FP;
#pragma unroll
        for (int n_ = 0; n_ < 8; n_++) {
            float p0 = __expf(sacc[n_][0] - mn0);
            float p1 = __expf(sacc[n_][1] - mn0);
            float p2 = __expf(sacc[n_][2] - mn1);
            float p3 = __expf(sacc[n_][3] - mn1);
            rs0 += p0 + p1; rs1 += p2 + p3;
            uint2 lo = make_uint2(f2tf32(p0), f2tf32(p1));
            uint2 hi = make_uint2(f2tf32(p2), f2tf32(p3));
            *(uint2*)(Ps + pbase + gid * FP + n_ * 8 + tg * 2)       = lo;
            *(uint2*)(Ps + pbase + (gid + 8) * FP + n_ * 8 + tg * 2) = hi;
        }
        rs0 += __shfl_xor_sync(0xffffffffu, rs0, 1);
        rs0 += __shfl_xor_sync(0xffffffffu, rs0, 2);
        rs1 += __shfl_xor_sync(0xffffffffu, rs1, 1);
        rs1 += __shfl_xor_sync(0xffffffffu, rs1, 2);
        l0r = l0r * al0 + rs0;
        l1r = l1r * al1 + rs1;

#pragma unroll
        for (int n_ = 0; n_ < 8; n_++) {
            o[n_][0] *= al0; o[n_][1] *= al0;
            o[n_][2] *= al1; o[n_][3] *= al1;
        }
        __syncwarp();

        // ---- O += P @ V  (A = warp-private P via LDSM, B = Vt) ----
        const uint32_t paddr = smb + PS_OFF * 4 + aoff;
#pragma unroll
        for (int ks = 0; ks < 8; ks++) {
            uint32_t pf[4];
            LDSM_X4(pf, paddr + ks * 32);
#pragma unroll
            for (int np = 0; np < 4; np++) {
                uint32_t bf[4];
                LDSM_X4(bf, vbase + np * 16 * FP * 4 + ks * 32);
                mma_1688(o[2*np],     pf, bf[0], bf[1]);
                mma_1688(o[2*np + 1], pf, bf[2], bf[3]);
            }
        }
        __syncthreads();   // reads of buf bb done before refill
    }

    // ---- epilogue: normalize, tf32-round, store ----
    const float inv0 = 1.0f / l0r, inv1 = 1.0f / l1r;
    float* Og = g_attn + (size_t)(b * SS + q0 + wq) * CC + h * DD;
#pragma unroll
    for (int n_ = 0; n_ < 8; n_++) {
        int col = n_ * 8 + tg * 2;
        uint2 lo = make_uint2(f2tf32(o[n_][0] * inv0), f2tf32(o[n_][1] * inv0));
        uint2 hi = make_uint2(f2tf32(o[n_][2] * inv1), f2tf32(o[n_][3] * inv1));
        *(uint2*)(Og + (size_t)gid * CC + col)       = lo;
        *(uint2*)(Og + (size_t)(gid + 8) * CC + col) = hi;
    }
}

// ---------------------------------------------------------------------------
extern "C" void kernel_launch(void* const* d_in, const int* in_sizes, int n_in,
                              void* d_out, int out_size)
{
    (void)in_sizes; (void)n_in; (void)out_size;
    const float* X  = (const float*)d_in[0];
    const float* Wq = (const float*)d_in[1];
    const float* Wk = (const float*)d_in[2];
    const float* Wv = (const float*)d_in[3];
    const float* Wo = (const float*)d_in[4];
    const float* bo = (const float*)d_in[5];
    float* out = (float*)d_out;

    cudaFuncSetAttribute(k_attn_mma, cudaFuncAttributeMaxDynamicSharedMemorySize,
                         ATT_SMEM);

    k_cvt<<<(CVT_F4 + 255) / 256, 256>>>(X, Wq, Wk, Wv, Wo);
    k_qkv_mma<<<dim3(CC / 128, (BB * SS) / 128, 3), 256>>>();
    k_transv<<<dim3(SS / 32, DD / 32, BB * HH), dim3(32, 8)>>>();
    k_stats<<<dim3(CC / 128, BB, 16), 128>>>();
    k_finalize<<<(2 * BB * CC + 255) / 256, 256>>>();
    k_apply<<<(2 * BB * SS * CC / 4 + 255) / 256, 256>>>();
    k_attn_mma<<<dim3(SS / 128, BB * HH), 256, ATT_SMEM>>>();
    k_proj_mma<<<dim3(CC / 128, (BB * SS) / 128), 256>>>(bo, out);
}

// round 9
// speedup vs baseline: 3.4220x; 1.0052x over previous
#include <cuda_runtime.h>
#include <cstdint>
#include <math.h>

// Problem constants
#define BB 4
#define SS 1024
#define CC 1280
#define HH 20
#define DD 64
#define ATT_SCALE 0.125f              // 64^-0.5
#define SC2 0.18033688011112042f      // ATT_SCALE * log2(e)
#define EPSV 1e-5f

// ---------------- scratch (static device allocations are allowed) -----------
#define XN (BB*SS*CC)     // 5242880
#define WN (CC*CC)        // 1638400
__device__ float g_tf[XN + 4*WN];     // tf32-rounded [X | Wq | Wk | Wv | Wo]
__device__ float g_q[BB*SS*CC];
__device__ float g_k[BB*SS*CC];
__device__ float g_v[BB*SS*CC];
__device__ float g_vt[BB*SS*CC];      // V transposed (tf32-rounded): [b][h][d][s]
__device__ float g_attn[BB*SS*CC];    // tf32-rounded attention output
__device__ float g_psum[2*BB*16*CC];  // stats partials: [z][b][seg][c]
__device__ float g_psq [2*BB*16*CC];
__device__ float g_scl[2*BB*CC];
__device__ float g_shf[2*BB*CC];

// =================== helpers (sm_75+/sm_80+ PTX, base-target safe) =========
__device__ __forceinline__ uint32_t f2tf32(float x) {
    uint32_t r;
    asm("cvt.rna.tf32.f32 %0, %1;" : "=r"(r) : "f"(x));
    return r;
}

__device__ __forceinline__ float fexp2(float x) {
    float y;
    asm("ex2.approx.f32 %0, %1;" : "=f"(y) : "f"(x));
    return y;
}

__device__ __forceinline__ void mma_1688(
    float c[4], const uint32_t a[4], uint32_t b0, uint32_t b1)
{
    asm volatile(
        "mma.sync.aligned.m16n8k8.row.col.f32.tf32.tf32.f32 "
        "{%0,%1,%2,%3}, {%4,%5,%6,%7}, {%8,%9}, {%0,%1,%2,%3};\n"
        : "+f"(c[0]), "+f"(c[1]), "+f"(c[2]), "+f"(c[3])
        : "r"(a[0]), "r"(a[1]), "r"(a[2]), "r"(a[3]), "r"(b0), "r"(b1));
}

__device__ __forceinline__ uint32_t smem_u32(const void* p) {
    uint32_t a;
    asm("{ .reg .u64 t; cvta.to.shared.u64 t, %1; cvt.u32.u64 %0, t; }"
        : "=r"(a) : "l"(p));
    return a;
}

#define LDSM_X4(R, addr) \
    asm volatile("ldmatrix.sync.aligned.m8n8.x4.shared.b16 {%0,%1,%2,%3}, [%4];" \
        : "=r"((R)[0]), "=r"((R)[1]), "=r"((R)[2]), "=r"((R)[3]) : "r"(addr))

#define CP_ASYNC16(dst, src) \
    asm volatile("cp.async.cg.shared.global [%0], [%1], 16;" \
        :: "r"(dst), "l"(src))
#define CP_COMMIT() asm volatile("cp.async.commit_group;")
#define CP_WAIT1()  asm volatile("cp.async.wait_group 1;")

// ---------------------------------------------------------------------------
// tf32 pre-rounding pass over [X | Wq | Wk | Wv | Wo]
// ---------------------------------------------------------------------------
#define CVT_F4 ((XN + 4*WN) / 4)
__global__ __launch_bounds__(256) void k_cvt(
    const float* __restrict__ X,  const float* __restrict__ Wq,
    const float* __restrict__ Wk, const float* __restrict__ Wv,
    const float* __restrict__ Wo)
{
    int i4 = blockIdx.x * 256 + threadIdx.x;
    if (i4 >= CVT_F4) return;
    const float* src;
    int base;
    if      (i4 < XN/4)          { src = X;  base = 0; }
    else if (i4 < (XN+WN)/4)     { src = Wq; base = XN/4; }
    else if (i4 < (XN+2*WN)/4)   { src = Wk; base = (XN+WN)/4; }
    else if (i4 < (XN+3*WN)/4)   { src = Wv; base = (XN+2*WN)/4; }
    else                         { src = Wo; base = (XN+3*WN)/4; }
    float4 v = ((const float4*)src)[i4 - base];
    uint4 t = make_uint4(f2tf32(v.x), f2tf32(v.y), f2tf32(v.z), f2tf32(v.w));
    ((uint4*)g_tf)[i4] = t;
}

// ---------------------------------------------------------------------------
// Tensor-core tf32 GEMM, LDSM fragments, 3-stage cp.async pipeline,
// ONE barrier per k-tile. Block 128x128, BK=16, 256 threads / 8 warps.
// Dynamic smem: 3 stages x (A 10240B + B 10240B) = 61440B.
// ---------------------------------------------------------------------------
#define BKP 20
#define GKT (CC / 16)   // 80 k-tiles
#define GST 10240       // bytes per operand-stage
#define GBOFF 30720     // B region offset
#define GEMM_SMEM 61440

#define GISSUE(t, s) do { \
    uint32_t _da = base + (s) * GST + stoff; \
    uint32_t _db = base + GBOFF + (s) * GST + stoff; \
    const float* _An = Ap + (t) * 16; \
    const float* _Bn = Bp + (t) * 16; \
    CP_ASYNC16(_da,      _An); \
    CP_ASYNC16(_da + 16, _An + 4); \
    CP_ASYNC16(_db,      _Bn); \
    CP_ASYNC16(_db + 16, _Bn + 4); \
} while (0)

__device__ __forceinline__ void gemm_mma_body(
    const float* __restrict__ A, const float* __restrict__ W,
    const float* __restrict__ bias, float* __restrict__ Cout)
{
    extern __shared__ __align__(16) uint32_t gsm[];

    const int tid  = threadIdx.x;
    const int warp = tid >> 5, lane = tid & 31;
    const int wm   = (warp & 3) * 32;
    const int wn   = (warp >> 2) * 64;
    const int tg   = lane & 3, gid = lane >> 2;
    const int m0   = blockIdx.y * 128;
    const int n0   = blockIdx.x * 128;

    const int lrow = tid >> 1;
    const int lc   = (tid & 1) * 8;
    const float* Ap = A + (size_t)(m0 + lrow) * CC + lc;
    const float* Bp = W + (size_t)(n0 + lrow) * CC + lc;

    const uint32_t base  = smem_u32(gsm);
    const uint32_t stoff = (uint32_t)(lrow * BKP + lc) * 4;

    const int lr = lane & 7;
    const uint32_t aoff = ((wm + ((lane >> 3) & 1) * 8 + lr) * BKP
                           + ((lane >> 4) & 1) * 4) * 4;
    const uint32_t boff = ((wn + (lane >> 4) * 8 + lr) * BKP
                           + ((lane >> 3) & 1) * 4) * 4;

    float acc[2][8][4];
#pragma unroll
    for (int im = 0; im < 2; im++)
#pragma unroll
        for (int in_ = 0; in_ < 8; in_++)
#pragma unroll
            for (int r = 0; r < 4; r++) acc[im][in_][r] = 0.f;

    GISSUE(0, 0); CP_COMMIT();
    GISSUE(1, 1); CP_COMMIT();

    int cs = 0;
    for (int kt = 0; kt < GKT; kt++) {
        CP_WAIT1();
        __syncthreads();

        int is_ = cs + 2; if (is_ >= 3) is_ -= 3;
        if (kt + 2 < GKT) GISSUE(kt + 2, is_);
        CP_COMMIT();

        const uint32_t sal = base + cs * GST + aoff;
        const uint32_t sbl = base + GBOFF + cs * GST + boff;
#pragma unroll
        for (int ks = 0; ks < 16; ks += 8) {
            uint32_t af[2][4];
            LDSM_X4(af[0], sal + ks * 4);
            LDSM_X4(af[1], sal + 16 * BKP * 4 + ks * 4);
#pragma unroll
            for (int np = 0; np < 4; np++) {
                uint32_t bf[4];
                LDSM_X4(bf, sbl + np * 16 * BKP * 4 + ks * 4);
                mma_1688(acc[0][2*np],     af[0], bf[0], bf[1]);
                mma_1688(acc[0][2*np + 1], af[0], bf[2], bf[3]);
                mma_1688(acc[1][2*np],     af[1], bf[0], bf[1]);
                mma_1688(acc[1][2*np + 1], af[1], bf[2], bf[3]);
            }
        }
        if (++cs == 3) cs = 0;
    }

#pragma unroll
    for (int im = 0; im < 2; im++) {
        int row = m0 + wm + im * 16 + gid;
#pragma unroll
        for (int in_ = 0; in_ < 8; in_++) {
            int col = n0 + wn + in_ * 8 + tg * 2;
            float b0v = 0.f, b1v = 0.f;
            if (bias) { b0v = bias[col]; b1v = bias[col + 1]; }
            float2 lo = make_float2(acc[im][in_][0] + b0v, acc[im][in_][1] + b1v);
            float2 hi = make_float2(acc[im][in_][2] + b0v, acc[im][in_][3] + b1v);
            *(float2*)(Cout + (size_t)row * CC + col)       = lo;
            *(float2*)(Cout + (size_t)(row + 8) * CC + col) = hi;
        }
    }
}

__global__ __launch_bounds__(256) void k_qkv_mma()
{
    const float* X = g_tf;
    const float* W = g_tf + XN + (size_t)blockIdx.z * WN;
    float* O;
    if (blockIdx.z == 0)      O = g_q;
    else if (blockIdx.z == 1) O = g_k;
    else                      O = g_v;
    gemm_mma_body(X, W, nullptr, O);
}

__global__ __launch_bounds__(256) void k_proj_mma(
    const float* __restrict__ bo, float* __restrict__ out)
{
    gemm_mma_body(g_attn, g_tf + XN + 3 * (size_t)WN, bo, out);
}

// ---------------------------------------------------------------------------
// V transpose + tf32 round: g_v [b][s][h][d] -> g_vt [b][h][d][s]
// ---------------------------------------------------------------------------
__global__ __launch_bounds__(256) void k_transv()
{
    __shared__ float tile[32][33];
    const int bh = blockIdx.z;
    const int b  = bh / HH, h = bh % HH;
    const int s0 = blockIdx.x * 32;
    const int d0 = blockIdx.y * 32;
    const int tx = threadIdx.x, ty = threadIdx.y;

    const float* src = g_v + (size_t)(b * SS + s0) * CC + h * DD + d0;
#pragma unroll
    for (int j = 0; j < 32; j += 8)
        tile[ty + j][tx] = src[(size_t)(ty + j) * CC + tx];
    __syncthreads();

    float* dst = g_vt + ((size_t)(b * HH + h) * DD + d0) * SS + s0;
#pragma unroll
    for (int j = 0; j < 32; j += 8)
        dst[(size_t)(ty + j) * SS + tx] = __uint_as_float(f2tf32(tile[tx][ty + j]));
}

// ---------------------------------------------------------------------------
// AdaIN stats: split-S partials (16 segments of 64 rows).
// ---------------------------------------------------------------------------
__global__ void k_stats()
{
    const int c   = blockIdx.x * 128 + threadIdx.x;
    const int b   = blockIdx.y;
    const int z   = blockIdx.z >> 4;
    const int seg = blockIdx.z & 15;
    const float* src = z ? g_k : g_q;
    const float* p = src + ((size_t)b * SS + seg * 64) * CC + c;

    float s0 = 0, s1 = 0, q0 = 0, q1 = 0;
#pragma unroll 4
    for (int s = 0; s < 64; s += 2) {
        float x0 = p[(size_t)(s + 0) * CC];
        float x1 = p[(size_t)(s + 1) * CC];
        s0 += x0; q0 = fmaf(x0, x0, q0);
        s1 += x1; q1 = fmaf(x1, x1, q1);
    }
    int idx = ((z * BB + b) * 16 + seg) * CC + c;
    g_psum[idx] = s0 + s1;
    g_psq [idx] = q0 + q1;
}

__global__ void k_finalize()
{
    int i = blockIdx.x * 256 + threadIdx.x;   // (z*BB+b)*CC + c
    if (i >= 2 * BB * CC) return;
    int c  = i % CC;
    int b  = (i / CC) % BB;
    int z  = i / (CC * BB);
    int sb = (b < BB / 2) ? 0 : BB / 2;

    float sum = 0, sq = 0, sums = 0, sqs = 0;
#pragma unroll
    for (int seg = 0; seg < 16; seg++) {
        sum  += g_psum[((z * BB + b)  * 16 + seg) * CC + c];
        sq   += g_psq [((z * BB + b)  * 16 + seg) * CC + c];
        sums += g_psum[((z * BB + sb) * 16 + seg) * CC + c];
        sqs  += g_psq [((z * BB + sb) * 16 + seg) * CC + c];
    }
    float mean  = sum  * (1.0f / SS);
    float means = sums * (1.0f / SS);
    float sd  = sqrtf((sq  - sum  * mean ) * (1.0f / (SS - 1)) + EPSV);
    float sds = sqrtf((sqs - sums * means) * (1.0f / (SS - 1)) + EPSV);
    float scl = sds / sd;
    g_scl[i] = scl;
    g_shf[i] = means - mean * scl;
}

__global__ void k_apply()
{
    const int TOT4  = 2 * BB * SS * CC / 4;
    const int per_t = SS * CC / 4;
    int i4 = blockIdx.x * 256 + threadIdx.x;
    if (i4 >= TOT4) return;
    int zb = i4 / per_t;
    int r  = i4 % per_t;
    int c  = (r % (CC / 4)) * 4;
    float* buf = (zb < BB) ? g_q : g_k;
    int b = zb & 3;
    float4* p = (float4*)buf + (size_t)b * per_t + r;
    float4 scl = *(const float4*)&g_scl[zb * CC + c];
    float4 shf = *(const float4*)&g_shf[zb * CC + c];
    float4 x = *p;
    uint4 t;
    t.x = f2tf32(fmaf(x.x, scl.x, shf.x));
    t.y = f2tf32(fmaf(x.y, scl.y, shf.y));
    t.z = f2tf32(fmaf(x.z, scl.z, shf.z));
    t.w = f2tf32(fmaf(x.w, scl.w, shf.w));
    *(uint4*)p = t;
}

// ---------------------------------------------------------------------------
// Flash attention on tensor cores, LDSM fragments, cp.async K/V, MAX-FREE
// softmax (logits bounded; exp2 space, style bias = exactly +1.0).
// CTA: 128 queries of one (b,h). 8 warps x 16 q-rows. 32 chunks of 64 keys.
// ---------------------------------------------------------------------------
#define FP 68                       // smem pitch (words), 68 % 32 == 4
#define KS_OFF(b) ((b) * 128 * FP)
#define VS_OFF(b) ((b) * 128 * FP + 64 * FP)
#define PS_OFF    (256 * FP)
#define ATT_SMEM  (384 * FP * 4)    // 104448 bytes

__global__ __launch_bounds__(256, 2) void k_attn_mma()
{
    extern __shared__ uint32_t sm[];
    uint32_t* Ps = sm + PS_OFF;

    const int tid  = threadIdx.x;
    const int warp = tid >> 5, lane = tid & 31;
    const int tg   = lane & 3, gid = lane >> 2;
    const int bh   = blockIdx.y;
    const int b    = bh / HH;
    const int h    = bh % HH;
    const int q0   = blockIdx.x * 128;
    const int sbv  = (b < BB / 2) ? 0 : BB / 2;
    const int wq   = warp * 16;

    const uint32_t smb = smem_u32(sm);
    const int frow = tid >> 4, fc4 = tid & 15;

    const int lr = lane & 7;
    const uint32_t aoff = ((wq + ((lane >> 3) & 1) * 8 + lr) * FP
                           + ((lane >> 4) & 1) * 4) * 4;
    const uint32_t kvoff = (((lane >> 4) * 8 + lr) * FP
                           + ((lane >> 3) & 1) * 4) * 4;

    // ---- stage Q tile into Ps, grab frags ----
    {
        const float* Qg = g_q + (size_t)(b * SS + q0) * CC + h * DD;
#pragma unroll
        for (int i = 0; i < 8; i++) {
            int fid = tid + i * 256;
            int row = fid >> 4, c4 = fid & 15;
            *(uint4*)(Ps + row * FP + c4 * 4) =
                *(const uint4*)(Qg + (size_t)row * CC + c4 * 4);
        }
    }
    __syncthreads();

    uint32_t qf[8][4];
    {
        const uint32_t qaddr = smb + PS_OFF * 4 + aoff;
#pragma unroll
        for (int ks = 0; ks < 8; ks++) LDSM_X4(qf[ks], qaddr + ks * 32);
    }
    __syncthreads();

    float o[8][4];
#pragma unroll
    for (int n_ = 0; n_ < 8; n_++)
#pragma unroll
        for (int r = 0; r < 4; r++) o[n_][r] = 0.f;
    float l0r = 0.f, l1r = 0.f;

    const float* Kbase0 = g_k + (size_t)b * SS * CC + h * DD;
    const float* Kbase1 = g_k + (size_t)sbv * SS * CC + h * DD;
    const float* Vbase0 = g_vt + ((size_t)(b * HH + h) * DD) * SS;
    const float* Vbase1 = g_vt + ((size_t)(sbv * HH + h) * DD) * SS;

    // prologue: chunk 0 -> buffer 0
    {
        uint32_t kd = smb + (KS_OFF(0) + frow * FP + fc4 * 4) * 4;
        uint32_t vd = smb + (VS_OFF(0) + frow * FP + fc4 * 4) * 4;
#pragma unroll
        for (int i = 0; i < 4; i++) {
            int row = frow + i * 16;
            CP_ASYNC16(kd + i * 16 * FP * 4, Kbase0 + (size_t)row * CC + fc4 * 4);
            CP_ASYNC16(vd + i * 16 * FP * 4, Vbase0 + (size_t)row * SS + fc4 * 4);
        }
        CP_COMMIT();
    }

    for (int ch = 0; ch < 32; ch++) {
        const int   bb = ch & 1;
        const float b2 = (ch < 16) ? 0.f : 1.0f;   // log2(e)*ln2 == 1

        // prefetch chunk ch+1 into buf bb^1 (its readers finished at ch-1)
        if (ch + 1 < 32) {
            const int self2 = (ch + 1 < 16);
            const int kr2   = (self2 ? ch + 1 : ch - 15) * 64;
            const float* Kg = (self2 ? Kbase0 : Kbase1) + (size_t)kr2 * CC;
            const float* Vg = (self2 ? Vbase0 : Vbase1) + kr2;
            uint32_t kd = smb + (KS_OFF(bb ^ 1) + frow * FP + fc4 * 4) * 4;
            uint32_t vd = smb + (VS_OFF(bb ^ 1) + frow * FP + fc4 * 4) * 4;
#pragma unroll
            for (int i = 0; i < 4; i++) {
                int row = frow + i * 16;
                CP_ASYNC16(kd + i * 16 * FP * 4, Kg + (size_t)row * CC + fc4 * 4);
                CP_ASYNC16(vd + i * 16 * FP * 4, Vg + (size_t)row * SS + fc4 * 4);
            }
        }
        CP_COMMIT();
        CP_WAIT1();       // chunk ch landed (always-commit keeps tail correct)
        __syncthreads();

        const uint32_t kbase = smb + KS_OFF(bb) * 4 + kvoff;
        const uint32_t vbase = smb + VS_OFF(bb) * 4 + kvoff;

        // ---- S = Q @ K^T  (16 x 64 per warp) ----
        float sacc[8][4];
#pragma unroll
        for (int n_ = 0; n_ < 8; n_++)
#pragma unroll
            for (int r = 0; r < 4; r++) sacc[n_][r] = 0.f;

#pragma unroll
        for (int ks = 0; ks < 8; ks++) {
#pragma unroll
            for (int np = 0; np < 4; np++) {
                uint32_t bf[4];
                LDSM_X4(bf, kbase + np * 16 * FP * 4 + ks * 32);
                mma_1688(sacc[2*np],     qf[ks], bf[0], bf[1]);
                mma_1688(sacc[2*np + 1], qf[ks], bf[2], bf[3]);
            }
        }

        // ---- max-free softmax: p = 2^(s*SC2 + b2), thread-local partials ----
        float rs0 = 0.f, rs1 = 0.f;
        const uint32_t pbase = wq * FP;
#pragma unroll
        for (int n_ = 0; n_ < 8; n_++) {
            float p0 = fexp2(fmaf(sacc[n_][0], SC2, b2));
            float p1 = fexp2(fmaf(sacc[n_][1], SC2, b2));
            float p2 = fexp2(fmaf(sacc[n_][2], SC2, b2));
            float p3 = fexp2(fmaf(sacc[n_][3], SC2, b2));
            rs0 += p0 + p1; rs1 += p2 + p3;
            uint2 lo = make_uint2(f2tf32(p0), f2tf32(p1));
            uint2 hi = make_uint2(f2tf32(p2), f2tf32(p3));
            *(uint2*)(Ps + pbase + gid * FP + n_ * 8 + tg * 2)       = lo;
            *(uint2*)(Ps + pbase + (gid + 8) * FP + n_ * 8 + tg * 2) = hi;
        }
        l0r += rs0;
        l1r += rs1;
        __syncwarp();

        // ---- O += P @ V  (A = warp-private P via LDSM, B = Vt) ----
        const uint32_t paddr = smb + PS_OFF * 4 + aoff;
#pragma unroll
        for (int ks = 0; ks < 8; ks++) {
            uint32_t pf[4];
            LDSM_X4(pf, paddr + ks * 32);
#pragma unroll
            for (int np = 0; np < 4; np++) {
                uint32_t bf[4];
                LDSM_X4(bf, vbase + np * 16 * FP * 4 + ks * 32);
                mma_1688(o[2*np],     pf, bf[0], bf[1]);
                mma_1688(o[2*np + 1], pf, bf[2], bf[3]);
            }
        }
        __syncthreads();   // reads of buf bb done before refill next iter
    }

    // ---- epilogue: quad-reduce row sums, normalize, store ----
    l0r += __shfl_xor_sync(0xffffffffu, l0r, 1);
    l0r += __shfl_xor_sync(0xffffffffu, l0r, 2);
    l1r += __shfl_xor_sync(0xffffffffu, l1r, 1);
    l1r += __shfl_xor_sync(0xffffffffu, l1r, 2);
    const float inv0 = 1.0f / l0r, inv1 = 1.0f / l1r;
    float* Og = g_attn + (size_t)(b * SS + q0 + wq) * CC + h * DD;
#pragma unroll
    for (int n_ = 0; n_ < 8; n_++) {
        int col = n_ * 8 + tg * 2;
        uint2 lo = make_uint2(f2tf32(o[n_][0] * inv0), f2tf32(o[n_][1] * inv0));
        uint2 hi = make_uint2(f2tf32(o[n_][2] * inv1), f2tf32(o[n_][3] * inv1));
        *(uint2*)(Og + (size_t)gid * CC + col)       = lo;
        *(uint2*)(Og + (size_t)(gid + 8) * CC + col) = hi;
    }
}

// ---------------------------------------------------------------------------
extern "C" void kernel_launch(void* const* d_in, const int* in_sizes, int n_in,
                              void* d_out, int out_size)
{
    (void)in_sizes; (void)n_in; (void)out_size;
    const float* X  = (const float*)d_in[0];
    const float* Wq = (const float*)d_in[1];
    const float* Wk = (const float*)d_in[2];
    const float* Wv = (const float*)d_in[3];
    const float* Wo = (const float*)d_in[4];
    const float* bo = (const float*)d_in[5];
    float* out = (float*)d_out;

    cudaFuncSetAttribute(k_attn_mma, cudaFuncAttributeMaxDynamicSharedMemorySize,
                         ATT_SMEM);
    cudaFuncSetAttribute(k_qkv_mma, cudaFuncAttributeMaxDynamicSharedMemorySize,
                         GEMM_SMEM);
    cudaFuncSetAttribute(k_proj_mma, cudaFuncAttributeMaxDynamicSharedMemorySize,
                         GEMM_SMEM);

    k_cvt<<<(CVT_F4 + 255) / 256, 256>>>(X, Wq, Wk, Wv, Wo);
    k_qkv_mma<<<dim3(CC / 128, (BB * SS) / 128, 3), 256, GEMM_SMEM>>>();
    k_transv<<<dim3(SS / 32, DD / 32, BB * HH), dim3(32, 8)>>>();
    k_stats<<<dim3(CC / 128, BB, 32), 128>>>();
    k_finalize<<<(2 * BB * CC + 255) / 256, 256>>>();
    k_apply<<<(2 * BB * SS * CC / 4 + 255) / 256, 256>>>();
    k_attn_mma<<<dim3(SS / 128, BB * HH), 256, ATT_SMEM>>>();
    k_proj_mma<<<dim3(CC / 128, (BB * SS) / 128), 256, GEMM_SMEM>>>(bo, out);
}

// round 10
// speedup vs baseline: 3.8473x; 1.1243x over previous
#include <cuda_runtime.h>
#include <cstdint>
#include <math.h>

// Problem constants
#define BB 4
#define SS 1024
#define CC 1280
#define HH 20
#define DD 64
#define ATT_SCALE 0.125f              // 64^-0.5
#define SC2 0.18033688011112042f      // ATT_SCALE * log2(e)
#define EPSV 1e-5f

// ---------------- scratch (static device allocations are allowed) -----------
#define XN (BB*SS*CC)     // 5242880
#define WN (CC*CC)        // 1638400
__device__ float g_tf[XN + 4*WN];     // tf32-rounded [X | Wq | Wk | Wv | Wo]
__device__ float g_q[BB*SS*CC];
__device__ float g_k[BB*SS*CC];
__device__ float g_v[BB*SS*CC];
__device__ float g_vt[BB*SS*CC];      // V transposed (tf32-rounded): [b][h][d][s]
__device__ float g_attn[BB*SS*CC];    // tf32-rounded attention output
__device__ float g_psum[2*BB*16*CC];  // stats partials: [z][b][seg][c]
__device__ float g_psq [2*BB*16*CC];
__device__ float g_scl[2*BB*CC];
__device__ float g_shf[2*BB*CC];

// =================== helpers (sm_75+/sm_80+ PTX, base-target safe) =========
__device__ __forceinline__ uint32_t f2tf32(float x) {
    uint32_t r;
    asm("cvt.rna.tf32.f32 %0, %1;" : "=r"(r) : "f"(x));
    return r;
}

__device__ __forceinline__ float fexp2(float x) {
    float y;
    asm("ex2.approx.f32 %0, %1;" : "=f"(y) : "f"(x));
    return y;
}

__device__ __forceinline__ void mma_1688(
    float c[4], const uint32_t a[4], uint32_t b0, uint32_t b1)
{
    asm volatile(
        "mma.sync.aligned.m16n8k8.row.col.f32.tf32.tf32.f32 "
        "{%0,%1,%2,%3}, {%4,%5,%6,%7}, {%8,%9}, {%0,%1,%2,%3};\n"
        : "+f"(c[0]), "+f"(c[1]), "+f"(c[2]), "+f"(c[3])
        : "r"(a[0]), "r"(a[1]), "r"(a[2]), "r"(a[3]), "r"(b0), "r"(b1));
}

__device__ __forceinline__ uint32_t smem_u32(const void* p) {
    uint32_t a;
    asm("{ .reg .u64 t; cvta.to.shared.u64 t, %1; cvt.u32.u64 %0, t; }"
        : "=r"(a) : "l"(p));
    return a;
}

#define LDSM_X4(R, addr) \
    asm volatile("ldmatrix.sync.aligned.m8n8.x4.shared.b16 {%0,%1,%2,%3}, [%4];" \
        : "=r"((R)[0]), "=r"((R)[1]), "=r"((R)[2]), "=r"((R)[3]) : "r"(addr))

#define CP_ASYNC16(dst, src) \
    asm volatile("cp.async.cg.shared.global [%0], [%1], 16;" \
        :: "r"(dst), "l"(src))
#define CP_COMMIT() asm volatile("cp.async.commit_group;")
#define CP_WAIT1()  asm volatile("cp.async.wait_group 1;")

// ---------------------------------------------------------------------------
// tf32 pre-rounding pass over [X | Wq | Wk | Wv | Wo]
// ---------------------------------------------------------------------------
#define CVT_F4 ((XN + 4*WN) / 4)
__global__ __launch_bounds__(256) void k_cvt(
    const float* __restrict__ X,  const float* __restrict__ Wq,
    const float* __restrict__ Wk, const float* __restrict__ Wv,
    const float* __restrict__ Wo)
{
    int i4 = blockIdx.x * 256 + threadIdx.x;
    if (i4 >= CVT_F4) return;
    const float* src;
    int base;
    if      (i4 < XN/4)          { src = X;  base = 0; }
    else if (i4 < (XN+WN)/4)     { src = Wq; base = XN/4; }
    else if (i4 < (XN+2*WN)/4)   { src = Wk; base = (XN+WN)/4; }
    else if (i4 < (XN+3*WN)/4)   { src = Wv; base = (XN+2*WN)/4; }
    else                         { src = Wo; base = (XN+3*WN)/4; }
    float4 v = ((const float4*)src)[i4 - base];
    uint4 t = make_uint4(f2tf32(v.x), f2tf32(v.y), f2tf32(v.z), f2tf32(v.w));
    ((uint4*)g_tf)[i4] = t;
}

// ---------------------------------------------------------------------------
// Tensor-core tf32 GEMM, LDSM fragments, 3-stage cp.async pipeline,
// ONE barrier per k-tile. Block 128x128, BK=16, 256 threads / 8 warps.
// ---------------------------------------------------------------------------
#define BKP 20
#define GKT (CC / 16)   // 80 k-tiles
#define GST 10240       // bytes per operand-stage
#define GBOFF 30720     // B region offset
#define GEMM_SMEM 61440

#define GISSUE(t, s) do { \
    uint32_t _da = base + (s) * GST + stoff; \
    uint32_t _db = base + GBOFF + (s) * GST + stoff; \
    const float* _An = Ap + (t) * 16; \
    const float* _Bn = Bp + (t) * 16; \
    CP_ASYNC16(_da,      _An); \
    CP_ASYNC16(_da + 16, _An + 4); \
    CP_ASYNC16(_db,      _Bn); \
    CP_ASYNC16(_db + 16, _Bn + 4); \
} while (0)

__device__ __forceinline__ void gemm_mma_body(
    const float* __restrict__ A, const float* __restrict__ W,
    const float* __restrict__ bias, float* __restrict__ Cout)
{
    extern __shared__ __align__(16) uint32_t gsm[];

    const int tid  = threadIdx.x;
    const int warp = tid >> 5, lane = tid & 31;
    const int wm   = (warp & 3) * 32;
    const int wn   = (warp >> 2) * 64;
    const int tg   = lane & 3, gid = lane >> 2;
    const int m0   = blockIdx.y * 128;
    const int n0   = blockIdx.x * 128;

    const int lrow = tid >> 1;
    const int lc   = (tid & 1) * 8;
    const float* Ap = A + (size_t)(m0 + lrow) * CC + lc;
    const float* Bp = W + (size_t)(n0 + lrow) * CC + lc;

    const uint32_t base  = smem_u32(gsm);
    const uint32_t stoff = (uint32_t)(lrow * BKP + lc) * 4;

    const int lr = lane & 7;
    const uint32_t aoff = ((wm + ((lane >> 3) & 1) * 8 + lr) * BKP
                           + ((lane >> 4) & 1) * 4) * 4;
    const uint32_t boff = ((wn + (lane >> 4) * 8 + lr) * BKP
                           + ((lane >> 3) & 1) * 4) * 4;

    float acc[2][8][4];
#pragma unroll
    for (int im = 0; im < 2; im++)
#pragma unroll
        for (int in_ = 0; in_ < 8; in_++)
#pragma unroll
            for (int r = 0; r < 4; r++) acc[im][in_][r] = 0.f;

    GISSUE(0, 0); CP_COMMIT();
    GISSUE(1, 1); CP_COMMIT();

    int cs = 0;
    for (int kt = 0; kt < GKT; kt++) {
        CP_WAIT1();
        __syncthreads();

        int is_ = cs + 2; if (is_ >= 3) is_ -= 3;
        if (kt + 2 < GKT) GISSUE(kt + 2, is_);
        CP_COMMIT();

        const uint32_t sal = base + cs * GST + aoff;
        const uint32_t sbl = base + GBOFF + cs * GST + boff;
#pragma unroll
        for (int ks = 0; ks < 16; ks += 8) {
            uint32_t af[2][4];
            LDSM_X4(af[0], sal + ks * 4);
            LDSM_X4(af[1], sal + 16 * BKP * 4 + ks * 4);
#pragma unroll
            for (int np = 0; np < 4; np++) {
                uint32_t bf[4];
                LDSM_X4(bf, sbl + np * 16 * BKP * 4 + ks * 4);
                mma_1688(acc[0][2*np],     af[0], bf[0], bf[1]);
                mma_1688(acc[0][2*np + 1], af[0], bf[2], bf[3]);
                mma_1688(acc[1][2*np],     af[1], bf[0], bf[1]);
                mma_1688(acc[1][2*np + 1], af[1], bf[2], bf[3]);
            }
        }
        if (++cs == 3) cs = 0;
    }

#pragma unroll
    for (int im = 0; im < 2; im++) {
        int row = m0 + wm + im * 16 + gid;
#pragma unroll
        for (int in_ = 0; in_ < 8; in_++) {
            int col = n0 + wn + in_ * 8 + tg * 2;
            float b0v = 0.f, b1v = 0.f;
            if (bias) { b0v = bias[col]; b1v = bias[col + 1]; }
            float2 lo = make_float2(acc[im][in_][0] + b0v, acc[im][in_][1] + b1v);
            float2 hi = make_float2(acc[im][in_][2] + b0v, acc[im][in_][3] + b1v);
            *(float2*)(Cout + (size_t)row * CC + col)       = lo;
            *(float2*)(Cout + (size_t)(row + 8) * CC + col) = hi;
        }
    }
}

__global__ __launch_bounds__(256) void k_qkv_mma()
{
    const float* X = g_tf;
    const float* W = g_tf + XN + (size_t)blockIdx.z * WN;
    float* O;
    if (blockIdx.z == 0)      O = g_q;
    else if (blockIdx.z == 1) O = g_k;
    else                      O = g_v;
    gemm_mma_body(X, W, nullptr, O);
}

__global__ __launch_bounds__(256) void k_proj_mma(
    const float* __restrict__ bo, float* __restrict__ out)
{
    gemm_mma_body(g_attn, g_tf + XN + 3 * (size_t)WN, bo, out);
}

// ---------------------------------------------------------------------------
// V transpose + tf32 round: g_v [b][s][h][d] -> g_vt [b][h][d][s]
// ---------------------------------------------------------------------------
__global__ __launch_bounds__(256) void k_transv()
{
    __shared__ float tile[32][33];
    const int bh = blockIdx.z;
    const int b  = bh / HH, h = bh % HH;
    const int s0 = blockIdx.x * 32;
    const int d0 = blockIdx.y * 32;
    const int tx = threadIdx.x, ty = threadIdx.y;

    const float* src = g_v + (size_t)(b * SS + s0) * CC + h * DD + d0;
#pragma unroll
    for (int j = 0; j < 32; j += 8)
        tile[ty + j][tx] = src[(size_t)(ty + j) * CC + tx];
    __syncthreads();

    float* dst = g_vt + ((size_t)(b * HH + h) * DD + d0) * SS + s0;
#pragma unroll
    for (int j = 0; j < 32; j += 8)
        dst[(size_t)(ty + j) * SS + tx] = __uint_as_float(f2tf32(tile[tx][ty + j]));
}

// ---------------------------------------------------------------------------
// AdaIN stats: split-S partials (16 segments of 64 rows).
// ---------------------------------------------------------------------------
__global__ void k_stats()
{
    const int c   = blockIdx.x * 128 + threadIdx.x;
    const int b   = blockIdx.y;
    const int z   = blockIdx.z >> 4;
    const int seg = blockIdx.z & 15;
    const float* src = z ? g_k : g_q;
    const float* p = src + ((size_t)b * SS + seg * 64) * CC + c;

    float s0 = 0, s1 = 0, q0 = 0, q1 = 0;
#pragma unroll 4
    for (int s = 0; s < 64; s += 2) {
        float x0 = p[(size_t)(s + 0) * CC];
        float x1 = p[(size_t)(s + 1) * CC];
        s0 += x0; q0 = fmaf(x0, x0, q0);
        s1 += x1; q1 = fmaf(x1, x1, q1);
    }
    int idx = ((z * BB + b) * 16 + seg) * CC + c;
    g_psum[idx] = s0 + s1;
    g_psq [idx] = q0 + q1;
}

__global__ void k_finalize()
{
    int i = blockIdx.x * 256 + threadIdx.x;   // (z*BB+b)*CC + c
    if (i >= 2 * BB * CC) return;
    int c  = i % CC;
    int b  = (i / CC) % BB;
    int z  = i / (CC * BB);
    int sb = (b < BB / 2) ? 0 : BB / 2;

    float sum = 0, sq = 0, sums = 0, sqs = 0;
#pragma unroll
    for (int seg = 0; seg < 16; seg++) {
        sum  += g_psum[((z * BB + b)  * 16 + seg) * CC + c];
        sq   += g_psq [((z * BB + b)  * 16 + seg) * CC + c];
        sums += g_psum[((z * BB + sb) * 16 + seg) * CC + c];
        sqs  += g_psq [((z * BB + sb) * 16 + seg) * CC + c];
    }
    float mean  = sum  * (1.0f / SS);
    float means = sums * (1.0f / SS);
    float sd  = sqrtf((sq  - sum  * mean ) * (1.0f / (SS - 1)) + EPSV);
    float sds = sqrtf((sqs - sums * means) * (1.0f / (SS - 1)) + EPSV);
    float scl = sds / sd;
    g_scl[i] = scl;
    g_shf[i] = means - mean * scl;
}

__global__ void k_apply()
{
    const int TOT4  = 2 * BB * SS * CC / 4;
    const int per_t = SS * CC / 4;
    int i4 = blockIdx.x * 256 + threadIdx.x;
    if (i4 >= TOT4) return;
    int zb = i4 / per_t;
    int r  = i4 % per_t;
    int c  = (r % (CC / 4)) * 4;
    float* buf = (zb < BB) ? g_q : g_k;
    int b = zb & 3;
    float4* p = (float4*)buf + (size_t)b * per_t + r;
    float4 scl = *(const float4*)&g_scl[zb * CC + c];
    float4 shf = *(const float4*)&g_shf[zb * CC + c];
    float4 x = *p;
    uint4 t;
    t.x = f2tf32(fmaf(x.x, scl.x, shf.x));
    t.y = f2tf32(fmaf(x.y, scl.y, shf.y));
    t.z = f2tf32(fmaf(x.z, scl.z, shf.z));
    t.w = f2tf32(fmaf(x.w, scl.w, shf.w));
    *(uint4*)p = t;
}

// ---------------------------------------------------------------------------
// Flash attention on tensor cores, LDSM fragments, cp.async K/V, max-free
// softmax. STYLE DEDUP: for batches whose style source is themselves
// (b==style(b)), softmax([s, s+ln2]) @ [V;V] == softmax(s) @ V exactly,
// so those CTAs run 16 chunks instead of 32. Long CTAs (b=1,3) are mapped
// to low blockIdx.y so they schedule in wave 1.
// ---------------------------------------------------------------------------
#define FP 68                       // smem pitch (words), 68 % 32 == 4
#define KS_OFF(b) ((b) * 128 * FP)
#define VS_OFF(b) ((b) * 128 * FP + 64 * FP)
#define PS_OFF    (256 * FP)
#define ATT_SMEM  (384 * FP * 4)    // 104448 bytes

__global__ __launch_bounds__(256, 2) void k_attn_mma()
{
    extern __shared__ uint32_t sm[];
    uint32_t* Ps = sm + PS_OFF;

    const int tid  = threadIdx.x;
    const int warp = tid >> 5, lane = tid & 31;
    const int tg   = lane & 3, gid = lane >> 2;

    // remap: groups {0,1,2,3} -> batches {1,3,0,2}; long CTAs first
    const int yb = blockIdx.y;
    const int h  = yb % HH;
    const int grp = yb / HH;
    const int b  = (grp == 0) ? 1 : (grp == 1) ? 3 : (grp == 2) ? 0 : 2;

    const int q0   = blockIdx.x * 128;
    const int sbv  = (b < BB / 2) ? 0 : BB / 2;
    const int nch  = (b == sbv) ? 16 : 32;   // dedup for self-style batches
    const int wq   = warp * 16;

    const uint32_t smb = smem_u32(sm);
    const int frow = tid >> 4, fc4 = tid & 15;

    const int lr = lane & 7;
    const uint32_t aoff = ((wq + ((lane >> 3) & 1) * 8 + lr) * FP
                           + ((lane >> 4) & 1) * 4) * 4;
    const uint32_t kvoff = (((lane >> 4) * 8 + lr) * FP
                           + ((lane >> 3) & 1) * 4) * 4;

    // ---- stage Q tile into Ps, grab frags ----
    {
        const float* Qg = g_q + (size_t)(b * SS + q0) * CC + h * DD;
#pragma unroll
        for (int i = 0; i < 8; i++) {
            int fid = tid + i * 256;
            int row = fid >> 4, c4 = fid & 15;
            *(uint4*)(Ps + row * FP + c4 * 4) =
                *(const uint4*)(Qg + (size_t)row * CC + c4 * 4);
        }
    }
    __syncthreads();

    uint32_t qf[8][4];
    {
        const uint32_t qaddr = smb + PS_OFF * 4 + aoff;
#pragma unroll
        for (int ks = 0; ks < 8; ks++) LDSM_X4(qf[ks], qaddr + ks * 32);
    }
    __syncthreads();

    float o[8][4];
#pragma unroll
    for (int n_ = 0; n_ < 8; n_++)
#pragma unroll
        for (int r = 0; r < 4; r++) o[n_][r] = 0.f;
    float l0r = 0.f, l1r = 0.f;

    const float* Kbase0 = g_k + (size_t)b * SS * CC + h * DD;
    const float* Kbase1 = g_k + (size_t)sbv * SS * CC + h * DD;
    const float* Vbase0 = g_vt + ((size_t)(b * HH + h) * DD) * SS;
    const float* Vbase1 = g_vt + ((size_t)(sbv * HH + h) * DD) * SS;

    // prologue: chunk 0 -> buffer 0
    {
        uint32_t kd = smb + (KS_OFF(0) + frow * FP + fc4 * 4) * 4;
        uint32_t vd = smb + (VS_OFF(0) + frow * FP + fc4 * 4) * 4;
#pragma unroll
        for (int i = 0; i < 4; i++) {
            int row = frow + i * 16;
            CP_ASYNC16(kd + i * 16 * FP * 4, Kbase0 + (size_t)row * CC + fc4 * 4);
            CP_ASYNC16(vd + i * 16 * FP * 4, Vbase0 + (size_t)row * SS + fc4 * 4);
        }
        CP_COMMIT();
    }

    for (int ch = 0; ch < nch; ch++) {
        const int   bb = ch & 1;
        const float b2 = (ch < 16) ? 0.f : 1.0f;   // log2(e)*ln2 == 1

        // prefetch chunk ch+1 into buf bb^1
        if (ch + 1 < nch) {
            const int self2 = (ch + 1 < 16);
            const int kr2   = (self2 ? ch + 1 : ch - 15) * 64;
            const float* Kg = (self2 ? Kbase0 : Kbase1) + (size_t)kr2 * CC;
            const float* Vg = (self2 ? Vbase0 : Vbase1) + kr2;
            uint32_t kd = smb + (KS_OFF(bb ^ 1) + frow * FP + fc4 * 4) * 4;
            uint32_t vd = smb + (VS_OFF(bb ^ 1) + frow * FP + fc4 * 4) * 4;
#pragma unroll
            for (int i = 0; i < 4; i++) {
                int row = frow + i * 16;
                CP_ASYNC16(kd + i * 16 * FP * 4, Kg + (size_t)row * CC + fc4 * 4);
                CP_ASYNC16(vd + i * 16 * FP * 4, Vg + (size_t)row * SS + fc4 * 4);
            }
        }
        CP_COMMIT();
        CP_WAIT1();
        __syncthreads();

        const uint32_t kbase = smb + KS_OFF(bb) * 4 + kvoff;
        const uint32_t vbase = smb + VS_OFF(bb) * 4 + kvoff;

        // ---- S = Q @ K^T  (16 x 64 per warp) ----
        float sacc[8][4];
#pragma unroll
        for (int n_ = 0; n_ < 8; n_++)
#pragma unroll
            for (int r = 0; r < 4; r++) sacc[n_][r] = 0.f;

#pragma unroll
        for (int ks = 0; ks < 8; ks++) {
#pragma unroll
            for (int np = 0; np < 4; np++) {
                uint32_t bf[4];
                LDSM_X4(bf, kbase + np * 16 * FP * 4 + ks * 32);
                mma_1688(sacc[2*np],     qf[ks], bf[0], bf[1]);
                mma_1688(sacc[2*np + 1], qf[ks], bf[2], bf[3]);
            }
        }

        // ---- max-free softmax: p = 2^(s*SC2 + b2), thread-local partials ----
        float rs0 = 0.f, rs1 = 0.f;
        const uint32_t pbase = wq * FP;
#pragma unroll
        for (int n_ = 0; n_ < 8; n_++) {
            float p0 = fexp2(fmaf(sacc[n_][0], SC2, b2));
            float p1 = fexp2(fmaf(sacc[n_][1], SC2, b2));
            float p2 = fexp2(fmaf(sacc[n_][2], SC2, b2));
            float p3 = fexp2(fmaf(sacc[n_][3], SC2, b2));
            rs0 += p0 + p1; rs1 += p2 + p3;
            uint2 lo = make_uint2(f2tf32(p0), f2tf32(p1));
            uint2 hi = make_uint2(f2tf32(p2), f2tf32(p3));
            *(uint2*)(Ps + pbase + gid * FP + n_ * 8 + tg * 2)       = lo;
            *(uint2*)(Ps + pbase + (gid + 8) * FP + n_ * 8 + tg * 2) = hi;
        }
        l0r += rs0;
        l1r += rs1;
        __syncwarp();

        // ---- O += P @ V  (A = warp-private P via LDSM, B = Vt) ----
        const uint32_t paddr = smb + PS_OFF * 4 + aoff;
#pragma unroll
        for (int ks = 0; ks < 8; ks++) {
            uint32_t pf[4];
            LDSM_X4(pf, paddr + ks * 32);
#pragma unroll
            for (int np = 0; np < 4; np++) {
                uint32_t bf[4];
                LDSM_X4(bf, vbase + np * 16 * FP * 4 + ks * 32);
                mma_1688(o[2*np],     pf, bf[0], bf[1]);
                mma_1688(o[2*np + 1], pf, bf[2], bf[3]);
            }
        }
        __syncthreads();   // reads of buf bb done before refill next iter
    }

    // ---- epilogue: quad-reduce row sums, normalize, store ----
    l0r += __shfl_xor_sync(0xffffffffu, l0r, 1);
    l0r += __shfl_xor_sync(0xffffffffu, l0r, 2);
    l1r += __shfl_xor_sync(0xffffffffu, l1r, 1);
    l1r += __shfl_xor_sync(0xffffffffu, l1r, 2);
    const float inv0 = 1.0f / l0r, inv1 = 1.0f / l1r;
    float* Og = g_attn + (size_t)(b * SS + q0 + wq) * CC + h * DD;
#pragma unroll
    for (int n_ = 0; n_ < 8; n_++) {
        int col = n_ * 8 + tg * 2;
        uint2 lo = make_uint2(f2tf32(o[n_][0] * inv0), f2tf32(o[n_][1] * inv0));
        uint2 hi = make_uint2(f2tf32(o[n_][2] * inv1), f2tf32(o[n_][3] * inv1));
        *(uint2*)(Og + (size_t)gid * CC + col)       = lo;
        *(uint2*)(Og + (size_t)(gid + 8) * CC + col) = hi;
    }
}

// ---------------------------------------------------------------------------
extern "C" void kernel_launch(void* const* d_in, const int* in_sizes, int n_in,
                              void* d_out, int out_size)
{
    (void)in_sizes; (void)n_in; (void)out_size;
    const float* X  = (const float*)d_in[0];
    const float* Wq = (const float*)d_in[1];
    const float* Wk = (const float*)d_in[2];
    const float* Wv = (const float*)d_in[3];
    const float* Wo = (const float*)d_in[4];
    const float* bo = (const float*)d_in[5];
    float* out = (float*)d_out;

    cudaFuncSetAttribute(k_attn_mma, cudaFuncAttributeMaxDynamicSharedMemorySize,
                         ATT_SMEM);
    cudaFuncSetAttribute(k_qkv_mma, cudaFuncAttributeMaxDynamicSharedMemorySize,
                         GEMM_SMEM);
    cudaFuncSetAttribute(k_proj_mma, cudaFuncAttributeMaxDynamicSharedMemorySize,
                         GEMM_SMEM);

    k_cvt<<<(CVT_F4 + 255) / 256, 256>>>(X, Wq, Wk, Wv, Wo);
    k_qkv_mma<<<dim3(CC / 128, (BB * SS) / 128, 3), 256, GEMM_SMEM>>>();
    k_transv<<<dim3(SS / 32, DD / 32, BB * HH), dim3(32, 8)>>>();
    k_stats<<<dim3(CC / 128, BB, 32), 128>>>();
    k_finalize<<<(2 * BB * CC + 255) / 256, 256>>>();
    k_apply<<<(2 * BB * SS * CC / 4 + 255) / 256, 256>>>();
    k_attn_mma<<<dim3(SS / 128, BB * HH), 256, ATT_SMEM>>>();
    k_proj_mma<<<dim3(CC / 128, (BB * SS) / 128), 256, GEMM_SMEM>>>(bo, out);
}

// round 11
// speedup vs baseline: 3.9234x; 1.0198x over previous
#include <cuda_runtime.h>
#include <cstdint>
#include <math.h>

// Problem constants
#define BB 4
#define SS 1024
#define CC 1280
#define HH 20
#define DD 64
#define ATT_SCALE 0.125f              // 64^-0.5
#define SC2 0.18033688011112042f      // ATT_SCALE * log2(e)
#define EPSV 1e-5f

// ---------------- scratch (static device allocations are allowed) -----------
#define XN (BB*SS*CC)     // 5242880
#define WN (CC*CC)        // 1638400
__device__ float g_tf[XN + 4*WN];     // tf32-rounded [X | Wq | Wk | Wv | Wo]
__device__ float g_q[BB*SS*CC];
__device__ float g_k[BB*SS*CC];
__device__ float g_v[BB*SS*CC];
__device__ float g_vt[BB*SS*CC];      // V transposed (tf32-rounded): [b][h][d][s]
__device__ float g_attn[BB*SS*CC];    // tf32-rounded attention output
__device__ float g_psum[2*BB*16*CC];  // stats partials: [z][b][seg][c]
__device__ float g_psq [2*BB*16*CC];
__device__ float g_scl[2*BB*CC];
__device__ float g_shf[2*BB*CC];

// =================== helpers (sm_75+/sm_80+ PTX, base-target safe) =========
__device__ __forceinline__ uint32_t f2tf32(float x) {
    uint32_t r;
    asm("cvt.rna.tf32.f32 %0, %1;" : "=r"(r) : "f"(x));
    return r;
}

__device__ __forceinline__ float fexp2(float x) {
    float y;
    asm("ex2.approx.f32 %0, %1;" : "=f"(y) : "f"(x));
    return y;
}

__device__ __forceinline__ void mma_1688(
    float c[4], const uint32_t a[4], uint32_t b0, uint32_t b1)
{
    asm volatile(
        "mma.sync.aligned.m16n8k8.row.col.f32.tf32.tf32.f32 "
        "{%0,%1,%2,%3}, {%4,%5,%6,%7}, {%8,%9}, {%0,%1,%2,%3};\n"
        : "+f"(c[0]), "+f"(c[1]), "+f"(c[2]), "+f"(c[3])
        : "r"(a[0]), "r"(a[1]), "r"(a[2]), "r"(a[3]), "r"(b0), "r"(b1));
}

__device__ __forceinline__ uint32_t smem_u32(const void* p) {
    uint32_t a;
    asm("{ .reg .u64 t; cvta.to.shared.u64 t, %1; cvt.u32.u64 %0, t; }"
        : "=r"(a) : "l"(p));
    return a;
}

#define LDSM_X4(R, addr) \
    asm volatile("ldmatrix.sync.aligned.m8n8.x4.shared.b16 {%0,%1,%2,%3}, [%4];" \
        : "=r"((R)[0]), "=r"((R)[1]), "=r"((R)[2]), "=r"((R)[3]) : "r"(addr))

#define CP_ASYNC16(dst, src) \
    asm volatile("cp.async.cg.shared.global [%0], [%1], 16;" \
        :: "r"(dst), "l"(src))
#define CP_COMMIT() asm volatile("cp.async.commit_group;")
#define CP_WAIT1()  asm volatile("cp.async.wait_group 1;")

// ---------------------------------------------------------------------------
// tf32 pre-rounding pass over [X | Wq | Wk | Wv | Wo]
// ---------------------------------------------------------------------------
#define CVT_F4 ((XN + 4*WN) / 4)
__global__ __launch_bounds__(256) void k_cvt(
    const float* __restrict__ X,  const float* __restrict__ Wq,
    const float* __restrict__ Wk, const float* __restrict__ Wv,
    const float* __restrict__ Wo)
{
    int i4 = blockIdx.x * 256 + threadIdx.x;
    if (i4 >= CVT_F4) return;
    const float* src;
    int base;
    if      (i4 < XN/4)          { src = X;  base = 0; }
    else if (i4 < (XN+WN)/4)     { src = Wq; base = XN/4; }
    else if (i4 < (XN+2*WN)/4)   { src = Wk; base = (XN+WN)/4; }
    else if (i4 < (XN+3*WN)/4)   { src = Wv; base = (XN+2*WN)/4; }
    else                         { src = Wo; base = (XN+3*WN)/4; }
    float4 v = ((const float4*)src)[i4 - base];
    uint4 t = make_uint4(f2tf32(v.x), f2tf32(v.y), f2tf32(v.z), f2tf32(v.w));
    ((uint4*)g_tf)[i4] = t;
}

// ---------------------------------------------------------------------------
// Tensor-core tf32 GEMM, LDSM fragments, 3-stage cp.async pipeline,
// ONE barrier per k-tile. Block 128x128, BK=16, 256 threads / 8 warps.
// ---------------------------------------------------------------------------
#define BKP 20
#define GKT (CC / 16)   // 80 k-tiles
#define GST 10240       // bytes per operand-stage
#define GBOFF 30720     // B region offset
#define GEMM_SMEM 61440

#define GISSUE(t, s) do { \
    uint32_t _da = base + (s) * GST + stoff; \
    uint32_t _db = base + GBOFF + (s) * GST + stoff; \
    const float* _An = Ap + (t) * 16; \
    const float* _Bn = Bp + (t) * 16; \
    CP_ASYNC16(_da,      _An); \
    CP_ASYNC16(_da + 16, _An + 4); \
    CP_ASYNC16(_db,      _Bn); \
    CP_ASYNC16(_db + 16, _Bn + 4); \
} while (0)

__device__ __forceinline__ void gemm_mma_body(
    const float* __restrict__ A, const float* __restrict__ W,
    const float* __restrict__ bias, float* __restrict__ Cout)
{
    extern __shared__ __align__(16) uint32_t gsm[];

    const int tid  = threadIdx.x;
    const int warp = tid >> 5, lane = tid & 31;
    const int wm   = (warp & 3) * 32;
    const int wn   = (warp >> 2) * 64;
    const int tg   = lane & 3, gid = lane >> 2;
    const int m0   = blockIdx.y * 128;
    const int n0   = blockIdx.x * 128;

    const int lrow = tid >> 1;
    const int lc   = (tid & 1) * 8;
    const float* Ap = A + (size_t)(m0 + lrow) * CC + lc;
    const float* Bp = W + (size_t)(n0 + lrow) * CC + lc;

    const uint32_t base  = smem_u32(gsm);
    const uint32_t stoff = (uint32_t)(lrow * BKP + lc) * 4;

    const int lr = lane & 7;
    const uint32_t aoff = ((wm + ((lane >> 3) & 1) * 8 + lr) * BKP
                           + ((lane >> 4) & 1) * 4) * 4;
    const uint32_t boff = ((wn + (lane >> 4) * 8 + lr) * BKP
                           + ((lane >> 3) & 1) * 4) * 4;

    float acc[2][8][4];
#pragma unroll
    for (int im = 0; im < 2; im++)
#pragma unroll
        for (int in_ = 0; in_ < 8; in_++)
#pragma unroll
            for (int r = 0; r < 4; r++) acc[im][in_][r] = 0.f;

    GISSUE(0, 0); CP_COMMIT();
    GISSUE(1, 1); CP_COMMIT();

    int cs = 0;
    for (int kt = 0; kt < GKT; kt++) {
        CP_WAIT1();
        __syncthreads();

        int is_ = cs + 2; if (is_ >= 3) is_ -= 3;
        if (kt + 2 < GKT) GISSUE(kt + 2, is_);
        CP_COMMIT();

        const uint32_t sal = base + cs * GST + aoff;
        const uint32_t sbl = base + GBOFF + cs * GST + boff;
#pragma unroll
        for (int ks = 0; ks < 16; ks += 8) {
            uint32_t af[2][4];
            LDSM_X4(af[0], sal + ks * 4);
            LDSM_X4(af[1], sal + 16 * BKP * 4 + ks * 4);
#pragma unroll
            for (int np = 0; np < 4; np++) {
                uint32_t bf[4];
                LDSM_X4(bf, sbl + np * 16 * BKP * 4 + ks * 4);
                mma_1688(acc[0][2*np],     af[0], bf[0], bf[1]);
                mma_1688(acc[0][2*np + 1], af[0], bf[2], bf[3]);
                mma_1688(acc[1][2*np],     af[1], bf[0], bf[1]);
                mma_1688(acc[1][2*np + 1], af[1], bf[2], bf[3]);
            }
        }
        if (++cs == 3) cs = 0;
    }

#pragma unroll
    for (int im = 0; im < 2; im++) {
        int row = m0 + wm + im * 16 + gid;
#pragma unroll
        for (int in_ = 0; in_ < 8; in_++) {
            int col = n0 + wn + in_ * 8 + tg * 2;
            float b0v = 0.f, b1v = 0.f;
            if (bias) { b0v = bias[col]; b1v = bias[col + 1]; }
            float2 lo = make_float2(acc[im][in_][0] + b0v, acc[im][in_][1] + b1v);
            float2 hi = make_float2(acc[im][in_][2] + b0v, acc[im][in_][3] + b1v);
            *(float2*)(Cout + (size_t)row * CC + col)       = lo;
            *(float2*)(Cout + (size_t)(row + 8) * CC + col) = hi;
        }
    }
}

__global__ __launch_bounds__(256) void k_qkv_mma()
{
    const float* X = g_tf;
    const float* W = g_tf + XN + (size_t)blockIdx.z * WN;
    float* O;
    if (blockIdx.z == 0)      O = g_q;
    else if (blockIdx.z == 1) O = g_k;
    else                      O = g_v;
    gemm_mma_body(X, W, nullptr, O);
}

__global__ __launch_bounds__(256) void k_proj_mma(
    const float* __restrict__ bo, float* __restrict__ out)
{
    gemm_mma_body(g_attn, g_tf + XN + 3 * (size_t)WN, bo, out);
}

// ---------------------------------------------------------------------------
// V transpose + tf32 round: g_v [b][s][h][d] -> g_vt [b][h][d][s]
// ---------------------------------------------------------------------------
__global__ __launch_bounds__(256) void k_transv()
{
    __shared__ float tile[32][33];
    const int bh = blockIdx.z;
    const int b  = bh / HH, h = bh % HH;
    const int s0 = blockIdx.x * 32;
    const int d0 = blockIdx.y * 32;
    const int tx = threadIdx.x, ty = threadIdx.y;

    const float* src = g_v + (size_t)(b * SS + s0) * CC + h * DD + d0;
#pragma unroll
    for (int j = 0; j < 32; j += 8)
        tile[ty + j][tx] = src[(size_t)(ty + j) * CC + tx];
    __syncthreads();

    float* dst = g_vt + ((size_t)(b * HH + h) * DD + d0) * SS + s0;
#pragma unroll
    for (int j = 0; j < 32; j += 8)
        dst[(size_t)(ty + j) * SS + tx] = __uint_as_float(f2tf32(tile[tx][ty + j]));
}

// ---------------------------------------------------------------------------
// AdaIN stats: split-S partials (16 segments of 64 rows).
// ---------------------------------------------------------------------------
__global__ void k_stats()
{
    const int c   = blockIdx.x * 128 + threadIdx.x;
    const int b   = blockIdx.y;
    const int z   = blockIdx.z >> 4;
    const int seg = blockIdx.z & 15;
    const float* src = z ? g_k : g_q;
    const float* p = src + ((size_t)b * SS + seg * 64) * CC + c;

    float s0 = 0, s1 = 0, q0 = 0, q1 = 0;
#pragma unroll 4
    for (int s = 0; s < 64; s += 2) {
        float x0 = p[(size_t)(s + 0) * CC];
        float x1 = p[(size_t)(s + 1) * CC];
        s0 += x0; q0 = fmaf(x0, x0, q0);
        s1 += x1; q1 = fmaf(x1, x1, q1);
    }
    int idx = ((z * BB + b) * 16 + seg) * CC + c;
    g_psum[idx] = s0 + s1;
    g_psq [idx] = q0 + q1;
}

__global__ void k_finalize()
{
    int i = blockIdx.x * 256 + threadIdx.x;   // (z*BB+b)*CC + c
    if (i >= 2 * BB * CC) return;
    int c  = i % CC;
    int b  = (i / CC) % BB;
    int z  = i / (CC * BB);
    int sb = (b < BB / 2) ? 0 : BB / 2;

    float sum = 0, sq = 0, sums = 0, sqs = 0;
#pragma unroll
    for (int seg = 0; seg < 16; seg++) {
        sum  += g_psum[((z * BB + b)  * 16 + seg) * CC + c];
        sq   += g_psq [((z * BB + b)  * 16 + seg) * CC + c];
        sums += g_psum[((z * BB + sb) * 16 + seg) * CC + c];
        sqs  += g_psq [((z * BB + sb) * 16 + seg) * CC + c];
    }
    float mean  = sum  * (1.0f / SS);
    float means = sums * (1.0f / SS);
    float sd  = sqrtf((sq  - sum  * mean ) * (1.0f / (SS - 1)) + EPSV);
    float sds = sqrtf((sqs - sums * means) * (1.0f / (SS - 1)) + EPSV);
    float scl = sds / sd;
    g_scl[i] = scl;
    g_shf[i] = means - mean * scl;
}

__global__ void k_apply()
{
    const int TOT4  = 2 * BB * SS * CC / 4;
    const int per_t = SS * CC / 4;
    int i4 = blockIdx.x * 256 + threadIdx.x;
    if (i4 >= TOT4) return;
    int zb = i4 / per_t;
    int r  = i4 % per_t;
    int c  = (r % (CC / 4)) * 4;
    float* buf = (zb < BB) ? g_q : g_k;
    int b = zb & 3;
    float4* p = (float4*)buf + (size_t)b * per_t + r;
    float4 scl = *(const float4*)&g_scl[zb * CC + c];
    float4 shf = *(const float4*)&g_shf[zb * CC + c];
    float4 x = *p;
    uint4 t;
    t.x = f2tf32(fmaf(x.x, scl.x, shf.x));
    t.y = f2tf32(fmaf(x.y, scl.y, shf.y));
    t.z = f2tf32(fmaf(x.z, scl.z, shf.z));
    t.w = f2tf32(fmaf(x.w, scl.w, shf.w));
    *(uint4*)p = t;
}

// ---------------------------------------------------------------------------
// Flash attention on tensor cores. 3-stage cp.async ring, ONE barrier per
// chunk, shuffle-built P fragments (no P smem round-trip). Style dedup:
// self-style batches run 16 chunks. Max-free softmax (exp2 space).
// CTA: 128 queries of one (b,h). 8 warps x 16 q-rows. Chunks of 64 keys.
// ---------------------------------------------------------------------------
#define FP 68                       // smem pitch (words), 68 % 32 == 4
#define KS_OFF(s) ((s) * 128 * FP)
#define VS_OFF(s) ((s) * 128 * FP + 64 * FP)
#define ATT_SMEM  (3 * 128 * FP * 4)    // 104448 bytes

__global__ __launch_bounds__(256, 2) void k_attn_mma()
{
    extern __shared__ uint32_t sm[];

    const int tid  = threadIdx.x;
    const int warp = tid >> 5, lane = tid & 31;
    const int tg   = lane & 3, gid = lane >> 2;

    // remap: groups {0,1,2,3} -> batches {1,3,0,2}; long CTAs first
    const int yb = blockIdx.y;
    const int h  = yb % HH;
    const int grp = yb / HH;
    const int b  = (grp == 0) ? 1 : (grp == 1) ? 3 : (grp == 2) ? 0 : 2;

    const int q0   = blockIdx.x * 128;
    const int sbv  = (b < BB / 2) ? 0 : BB / 2;
    const int nch  = (b == sbv) ? 16 : 32;   // dedup for self-style batches
    const int wq   = warp * 16;

    const uint32_t smb = smem_u32(sm);
    const int frow = tid >> 4, fc4 = tid & 15;

    const int lr = lane & 7;
    const uint32_t aoff = ((wq + ((lane >> 3) & 1) * 8 + lr) * FP
                           + ((lane >> 4) & 1) * 4) * 4;
    const uint32_t kvoff = (((lane >> 4) * 8 + lr) * FP
                           + ((lane >> 3) & 1) * 4) * 4;

    // shfl source lanes for P-fragment construction
    const int ps1 = (lane & 0x1C) | (tg >> 1);   // 4*gid + (tg>>1)
    const int ps2 = ps1 + 2;
    const int todd = tg & 1;

    // ---- stage Q tile through stage-0 region, grab frags ----
    {
        const float* Qg = g_q + (size_t)(b * SS + q0) * CC + h * DD;
#pragma unroll
        for (int i = 0; i < 8; i++) {
            int fid = tid + i * 256;
            int row = fid >> 4, c4 = fid & 15;
            *(uint4*)(sm + row * FP + c4 * 4) =
                *(const uint4*)(Qg + (size_t)row * CC + c4 * 4);
        }
    }
    __syncthreads();

    uint32_t qf[8][4];
#pragma unroll
    for (int ks = 0; ks < 8; ks++) LDSM_X4(qf[ks], smb + aoff + ks * 32);
    __syncthreads();   // Q reads done; stage 0 free for chunk 0

    float o[8][4];
#pragma unroll
    for (int n_ = 0; n_ < 8; n_++)
#pragma unroll
        for (int r = 0; r < 4; r++) o[n_][r] = 0.f;
    float l0r = 0.f, l1r = 0.f;

    const float* Kbase0 = g_k + (size_t)b * SS * CC + h * DD;
    const float* Kbase1 = g_k + (size_t)sbv * SS * CC + h * DD;
    const float* Vbase0 = g_vt + ((size_t)(b * HH + h) * DD) * SS;
    const float* Vbase1 = g_vt + ((size_t)(sbv * HH + h) * DD) * SS;

#define AISSUE(c, s) do { \
    const int _self = ((c) < 16); \
    const int _kr   = (_self ? (c) : (c) - 16) * 64; \
    const float* _Kg = (_self ? Kbase0 : Kbase1) + (size_t)_kr * CC; \
    const float* _Vg = (_self ? Vbase0 : Vbase1) + _kr; \
    uint32_t _kd = smb + (KS_OFF(s) + frow * FP + fc4 * 4) * 4; \
    uint32_t _vd = smb + (VS_OFF(s) + frow * FP + fc4 * 4) * 4; \
    _Pragma("unroll") \
    for (int _i = 0; _i < 4; _i++) { \
        int _row = frow + _i * 16; \
        CP_ASYNC16(_kd + _i * 16 * FP * 4, _Kg + (size_t)_row * CC + fc4 * 4); \
        CP_ASYNC16(_vd + _i * 16 * FP * 4, _Vg + (size_t)_row * SS + fc4 * 4); \
    } \
} while (0)

    // prologue: chunks 0,1 -> stages 0,1
    AISSUE(0, 0); CP_COMMIT();
    AISSUE(1, 1); CP_COMMIT();

    int st = 0;
    for (int ch = 0; ch < nch; ch++) {
        const float b2 = (ch < 16) ? 0.f : 1.0f;   // log2(e)*ln2 == 1

        CP_WAIT1();
        __syncthreads();   // chunk ch visible; refill target's readers done

        int is_ = st + 2; if (is_ >= 3) is_ -= 3;
        if (ch + 2 < nch) AISSUE(ch + 2, is_);
        CP_COMMIT();

        const uint32_t kbase = smb + KS_OFF(st) * 4 + kvoff;
        const uint32_t vbase = smb + VS_OFF(st) * 4 + kvoff;

        // ---- S = Q @ K^T  (16 x 64 per warp) ----
        float sacc[8][4];
#pragma unroll
        for (int n_ = 0; n_ < 8; n_++)
#pragma unroll
            for (int r = 0; r < 4; r++) sacc[n_][r] = 0.f;

#pragma unroll
        for (int ks = 0; ks < 8; ks++) {
#pragma unroll
            for (int np = 0; np < 4; np++) {
                uint32_t bf[4];
                LDSM_X4(bf, kbase + np * 16 * FP * 4 + ks * 32);
                mma_1688(sacc[2*np],     qf[ks], bf[0], bf[1]);
                mma_1688(sacc[2*np + 1], qf[ks], bf[2], bf[3]);
            }
        }

        // ---- fused softmax + PV: per k-block build P frags via shfl ----
#pragma unroll
        for (int kb = 0; kb < 8; kb++) {
            float e0 = fexp2(fmaf(sacc[kb][0], SC2, b2));
            float e1 = fexp2(fmaf(sacc[kb][1], SC2, b2));
            float e2 = fexp2(fmaf(sacc[kb][2], SC2, b2));
            float e3 = fexp2(fmaf(sacc[kb][3], SC2, b2));
            l0r += e0 + e1;
            l1r += e2 + e3;
            uint32_t p0 = f2tf32(e0), p1 = f2tf32(e1);
            uint32_t p2 = f2tf32(e2), p3 = f2tf32(e3);

            uint32_t pf[4];
            {
                uint32_t x0 = __shfl_sync(0xffffffffu, p0, ps1);
                uint32_t x1 = __shfl_sync(0xffffffffu, p1, ps1);
                pf[0] = todd ? x1 : x0;
                uint32_t y0 = __shfl_sync(0xffffffffu, p2, ps1);
                uint32_t y1 = __shfl_sync(0xffffffffu, p3, ps1);
                pf[1] = todd ? y1 : y0;
                uint32_t x2 = __shfl_sync(0xffffffffu, p0, ps2);
                uint32_t x3 = __shfl_sync(0xffffffffu, p1, ps2);
                pf[2] = todd ? x3 : x2;
                uint32_t y2 = __shfl_sync(0xffffffffu, p2, ps2);
                uint32_t y3 = __shfl_sync(0xffffffffu, p3, ps2);
                pf[3] = todd ? y3 : y2;
            }

#pragma unroll
            for (int np = 0; np < 4; np++) {
                uint32_t bf[4];
                LDSM_X4(bf, vbase + np * 16 * FP * 4 + kb * 32);
                mma_1688(o[2*np],     pf, bf[0], bf[1]);
                mma_1688(o[2*np + 1], pf, bf[2], bf[3]);
            }
        }

        if (++st == 3) st = 0;
    }

    // ---- epilogue: quad-reduce row sums, normalize, store ----
    l0r += __shfl_xor_sync(0xffffffffu, l0r, 1);
    l0r += __shfl_xor_sync(0xffffffffu, l0r, 2);
    l1r += __shfl_xor_sync(0xffffffffu, l1r, 1);
    l1r += __shfl_xor_sync(0xffffffffu, l1r, 2);
    const float inv0 = 1.0f / l0r, inv1 = 1.0f / l1r;
    float* Og = g_attn + (size_t)(b * SS + q0 + wq) * CC + h * DD;
#pragma unroll
    for (int n_ = 0; n_ < 8; n_++) {
        int col = n_ * 8 + tg * 2;
        uint2 lo = make_uint2(f2tf32(o[n_][0] * inv0), f2tf32(o[n_][1] * inv0));
        uint2 hi = make_uint2(f2tf32(o[n_][2] * inv1), f2tf32(o[n_][3] * inv1));
        *(uint2*)(Og + (size_t)gid * CC + col)       = lo;
        *(uint2*)(Og + (size_t)(gid + 8) * CC + col) = hi;
    }
}

// ---------------------------------------------------------------------------
extern "C" void kernel_launch(void* const* d_in, const int* in_sizes, int n_in,
                              void* d_out, int out_size)
{
    (void)in_sizes; (void)n_in; (void)out_size;
    const float* X  = (const float*)d_in[0];
    const float* Wq = (const float*)d_in[1];
    const float* Wk = (const float*)d_in[2];
    const float* Wv = (const float*)d_in[3];
    const float* Wo = (const float*)d_in[4];
    const float* bo = (const float*)d_in[5];
    float* out = (float*)d_out;

    cudaFuncSetAttribute(k_attn_mma, cudaFuncAttributeMaxDynamicSharedMemorySize,
                         ATT_SMEM);
    cudaFuncSetAttribute(k_qkv_mma, cudaFuncAttributeMaxDynamicSharedMemorySize,
                         GEMM_SMEM);
    cudaFuncSetAttribute(k_proj_mma, cudaFuncAttributeMaxDynamicSharedMemorySize,
                         GEMM_SMEM);

    k_cvt<<<(CVT_F4 + 255) / 256, 256>>>(X, Wq, Wk, Wv, Wo);
    k_qkv_mma<<<dim3(CC / 128, (BB * SS) / 128, 3), 256, GEMM_SMEM>>>();
    k_transv<<<dim3(SS / 32, DD / 32, BB * HH), dim3(32, 8)>>>();
    k_stats<<<dim3(CC / 128, BB, 32), 128>>>();
    k_finalize<<<(2 * BB * CC + 255) / 256, 256>>>();
    k_apply<<<(2 * BB * SS * CC / 4 + 255) / 256, 256>>>();
    k_attn_mma<<<dim3(SS / 128, BB * HH), 256, ATT_SMEM>>>();
    k_proj_mma<<<dim3(CC / 128, (BB * SS) / 128), 256, GEMM_SMEM>>>(bo, out);
}